// round 7
// baseline (speedup 1.0000x reference)
#include <cuda_runtime.h>
#include <cuda_fp16.h>
#include <mma.h>
#include <cstdint>

using namespace nvcuda;

// Problem constants
#define N_NODES 40000
#define NPAD    40064          // padded row count (multiple of 128)
#define N_EDGES 640000
#define D 128

// tile strides
#define KP 136           // half elements per row in A/W tiles (pad 8)
#define SP 132           // float elements per row in staging

// ---------------- device scratch ----------------
__device__ float g_h[NPAD * D];
__device__ float g_P[NPAD * 2 * D];
__device__ float g_msum[NPAD * D];
__device__ float g_cnt[NPAD];

// Pre-split fp16 weight tiles, layout [n][KP] (B col-major for wmma), hi/lo.
// Each tile: 128*KP halves = 34816 bytes.
__device__ __align__(32) half g_WcHi[128 * KP];   // msg_w1 rows [256,384)
__device__ __align__(32) half g_WcLo[128 * KP];
__device__ __align__(32) half g_W2Hi[128 * KP];   // msg_w2
__device__ __align__(32) half g_W2Lo[128 * KP];
__device__ __align__(32) half g_WaHi[128 * KP];   // msg_w1 rows [0,128)
__device__ __align__(32) half g_WaLo[128 * KP];
__device__ __align__(32) half g_WbHi[128 * KP];   // msg_w1 rows [128,256)
__device__ __align__(32) half g_WbLo[128 * KP];
__device__ __align__(32) half g_A1aHi[128 * KP];  // agg_w1 rows [0,128)
__device__ __align__(32) half g_A1aLo[128 * KP];
__device__ __align__(32) half g_A1bHi[128 * KP];  // agg_w1 rows [128,256)
__device__ __align__(32) half g_A1bLo[128 * KP];
__device__ __align__(32) half g_A2Hi[128 * KP];   // agg_w2
__device__ __align__(32) half g_A2Lo[128 * KP];

// ---------------- generic helpers ----------------
__device__ __forceinline__ float silu_f(float x) {
    return x / (1.0f + __expf(-x));
}

__device__ __forceinline__ void red_add4(float* p, float a, float b, float c, float d) {
    asm volatile("red.global.add.v4.f32 [%0], {%1, %2, %3, %4};"
                 :: "l"(p), "f"(a), "f"(b), "f"(c), "f"(d) : "memory");
}

__device__ __forceinline__ void split_h(float x, half &h, half &l) {
    h = __float2half_rn(x);
    l = __float2half_rn(x - __half2float(h));
}

__device__ __forceinline__ uint32_t pack_h2(half a, half b) {
    __half2 t = __halves2half2(a, b);
    return *reinterpret_cast<uint32_t*>(&t);
}

// ---------------- wmma building blocks ----------------
typedef wmma::fragment<wmma::accumulator, 16, 16, 16, float> FragC;
typedef wmma::fragment<wmma::matrix_a, 16, 16, 16, half, wmma::row_major> FragA;
typedef wmma::fragment<wmma::matrix_b, 16, 16, 16, half, wmma::col_major> FragB;

// c += Ahi*Bhi + Alo*Bhi + Ahi*Blo   (3-product split, ~1e-7 error)
__device__ __forceinline__ void gemm3_acc(const half* __restrict__ aHi,
                                          const half* __restrict__ aLo,
                                          const half* __restrict__ bHi,
                                          const half* __restrict__ bLo,
                                          FragC c[2][4], int wm, int wn) {
#pragma unroll
    for (int ks = 0; ks < 8; ++ks) {
        const int k0 = ks * 16;
        FragA ah[2], al[2];
#pragma unroll
        for (int i = 0; i < 2; ++i) {
            const int m0 = wm * 32 + i * 16;
            wmma::load_matrix_sync(ah[i], aHi + m0 * KP + k0, KP);
            wmma::load_matrix_sync(al[i], aLo + m0 * KP + k0, KP);
        }
#pragma unroll
        for (int j = 0; j < 4; ++j) {
            const int n0 = wn * 64 + j * 16;
            FragB bh, bl;
            wmma::load_matrix_sync(bh, bHi + n0 * KP + k0, KP);
            wmma::load_matrix_sync(bl, bLo + n0 * KP + k0, KP);
#pragma unroll
            for (int i = 0; i < 2; ++i) {
                wmma::mma_sync(c[i][j], ah[i], bh, c[i][j]);
                wmma::mma_sync(c[i][j], al[i], bh, c[i][j]);
                wmma::mma_sync(c[i][j], ah[i], bl, c[i][j]);
            }
        }
    }
}

// c += A*Bhi + A*Blo   (2-product: A single fp16, weights exactly split)
__device__ __forceinline__ void gemm2p_acc(const half* __restrict__ aH,
                                           const half* __restrict__ bHi,
                                           const half* __restrict__ bLo,
                                           FragC c[2][4], int wm, int wn) {
#pragma unroll
    for (int ks = 0; ks < 8; ++ks) {
        const int k0 = ks * 16;
        FragA ah[2];
#pragma unroll
        for (int i = 0; i < 2; ++i)
            wmma::load_matrix_sync(ah[i], aH + (wm * 32 + i * 16) * KP + k0, KP);
#pragma unroll
        for (int j = 0; j < 4; ++j) {
            const int n0 = wn * 64 + j * 16;
            FragB bh, bl;
            wmma::load_matrix_sync(bh, bHi + n0 * KP + k0, KP);
            wmma::load_matrix_sync(bl, bLo + n0 * KP + k0, KP);
#pragma unroll
            for (int i = 0; i < 2; ++i) {
                wmma::mma_sync(c[i][j], ah[i], bh, c[i][j]);
                wmma::mma_sync(c[i][j], ah[i], bl, c[i][j]);
            }
        }
    }
}

__device__ __forceinline__ void zero_frags(FragC c[2][4]) {
#pragma unroll
    for (int i = 0; i < 2; ++i)
#pragma unroll
        for (int j = 0; j < 4; ++j) wmma::fill_fragment(c[i][j], 0.0f);
}

__device__ __forceinline__ void store_stage(FragC c[2][4], float* st, int wm, int wn) {
#pragma unroll
    for (int i = 0; i < 2; ++i)
#pragma unroll
        for (int j = 0; j < 4; ++j)
            wmma::store_matrix_sync(st + (wm * 32 + i * 16) * SP + wn * 64 + j * 16,
                                    c[i][j], SP, wmma::mem_row_major);
}

// copy one 34816B weight tile global->smem (256 threads)
__device__ __forceinline__ void copy_tile(half* dst, const half* src, int tid) {
    uint4* d = (uint4*)dst;
    const uint4* s = (const uint4*)src;
#pragma unroll 2
    for (int idx = tid; idx < 2176; idx += 256) d[idx] = s[idx];
}

// ---------------- kernel: zero scratch (+ pad rows of g_h) ----------------
__global__ void zero_kernel() {
    int i = blockIdx.x * blockDim.x + threadIdx.x;
    const int total4 = NPAD * D / 4;
    if (i < total4) reinterpret_cast<float4*>(g_msum)[i] = make_float4(0.f, 0.f, 0.f, 0.f);
    if (i < NPAD) g_cnt[i] = 0.0f;
    if (i < (NPAD - N_NODES) * D / 4)
        reinterpret_cast<float4*>(g_h + N_NODES * D)[i] = make_float4(0.f, 0.f, 0.f, 0.f);
}

// ---------------- kernel: LayerNorm ----------------
__global__ void ln_kernel(const float* __restrict__ x,
                          const float* __restrict__ gamma,
                          const float* __restrict__ beta) {
    int warp = threadIdx.x >> 5;
    int lane = threadIdx.x & 31;
    int n = blockIdx.x * 8 + warp;
    float4 v = *reinterpret_cast<const float4*>(x + (size_t)n * D + lane * 4);
    float s = v.x + v.y + v.z + v.w;
#pragma unroll
    for (int o = 16; o > 0; o >>= 1) s += __shfl_xor_sync(0xffffffffu, s, o);
    float mu = s * (1.0f / D);
    float d0 = v.x - mu, d1 = v.y - mu, d2 = v.z - mu, d3 = v.w - mu;
    float ss = d0 * d0 + d1 * d1 + d2 * d2 + d3 * d3;
#pragma unroll
    for (int o = 16; o > 0; o >>= 1) ss += __shfl_xor_sync(0xffffffffu, ss, o);
    float rs = rsqrtf(ss * (1.0f / D) + 1e-5f);
    float4 g = *reinterpret_cast<const float4*>(gamma + lane * 4);
    float4 b = *reinterpret_cast<const float4*>(beta + lane * 4);
    float4 o4;
    o4.x = d0 * rs * g.x + b.x;
    o4.y = d1 * rs * g.y + b.y;
    o4.z = d2 * rs * g.z + b.z;
    o4.w = d3 * rs * g.w + b.w;
    *reinterpret_cast<float4*>(g_h + (size_t)n * D + lane * 4) = o4;
}

// ---------------- kernel: per-src edge counts ----------------
__global__ void cnt_kernel(const int* __restrict__ src) {
    int i = blockIdx.x * blockDim.x + threadIdx.x;
    if (i < N_EDGES) atomicAdd(&g_cnt[src[i]], 1.0f);
}

// ---------------- kernel: split all weights to fp16 hi/lo tiles ------------
__global__ void wprep_kernel(const float* __restrict__ mw1, const float* __restrict__ mw2,
                             const float* __restrict__ aw1, const float* __restrict__ aw2) {
    int i = blockIdx.x * blockDim.x + threadIdx.x;
    if (i >= 7 * 16384) return;
    int mat = i >> 14;
    int r = i & 16383;
    int n = r >> 7;
    int k = r & 127;
    float v;
    half *dh, *dl;
    switch (mat) {
        case 0: v = mw1[(256 + k) * 128 + n]; dh = g_WcHi;  dl = g_WcLo;  break;
        case 1: v = mw2[k * 128 + n];         dh = g_W2Hi;  dl = g_W2Lo;  break;
        case 2: v = mw1[k * 128 + n];         dh = g_WaHi;  dl = g_WaLo;  break;
        case 3: v = mw1[(128 + k) * 128 + n]; dh = g_WbHi;  dl = g_WbLo;  break;
        case 4: v = aw1[k * 128 + n];         dh = g_A1aHi; dl = g_A1aLo; break;
        case 5: v = aw1[(128 + k) * 128 + n]; dh = g_A1bHi; dl = g_A1bLo; break;
        default: v = aw2[k * 128 + n];        dh = g_A2Hi;  dl = g_A2Lo;  break;
    }
    half h, l;
    split_h(v, h, l);
    dh[n * KP + k] = h;
    dl[n * KP + k] = l;
}

// ---------------- kernel: node projections P = h @ [Wa|Wb] (wmma 3-split) ---
// smem: 4 weight tiles [0,139264) + A hi [139264,+34816) + A lo [174080,+34816)
#define PNODE_SMEM (208896 + 1024)
__global__ __launch_bounds__(256, 1)
void pnode_kernel() {
    extern __shared__ char smraw[];
    char* base = (char*)(((uintptr_t)smraw + 1023) & ~(uintptr_t)1023);
    half* sWaHi = (half*)(base + 0);
    half* sWaLo = (half*)(base + 34816);
    half* sWbHi = (half*)(base + 69632);
    half* sWbLo = (half*)(base + 104448);
    half* aHi   = (half*)(base + 139264);
    half* aLo   = (half*)(base + 174080);

    const int tid = threadIdx.x;
    const int wid = tid >> 5;
    const int wm = wid & 3;
    const int wn = wid >> 2;
    const int row = tid >> 1;
    const int c0 = (tid & 1) * 64;
    const int n0 = blockIdx.x * 128;

    copy_tile(sWaHi, g_WaHi, tid);
    copy_tile(sWaLo, g_WaLo, tid);
    copy_tile(sWbHi, g_WbHi, tid);
    copy_tile(sWbLo, g_WbLo, tid);

    // A = h tile, split hi/lo (padded globals: no bounds checks)
    {
        const float4* srcp = (const float4*)(g_h + (size_t)(n0 + row) * 128 + c0);
        half* dh = aHi + row * KP + c0;
        half* dl = aLo + row * KP + c0;
#pragma unroll
        for (int g = 0; g < 16; ++g) {
            float4 v = srcp[g];
            half h0, l0, h1, l1, h2, l2, h3, l3;
            split_h(v.x, h0, l0); split_h(v.y, h1, l1);
            split_h(v.z, h2, l2); split_h(v.w, h3, l3);
            *(uint2*)(dh + g * 4) = make_uint2(pack_h2(h0, h1), pack_h2(h2, h3));
            *(uint2*)(dl + g * 4) = make_uint2(pack_h2(l0, l1), pack_h2(l2, l3));
        }
    }
    __syncthreads();

#pragma unroll
    for (int hf = 0; hf < 2; ++hf) {
        FragC c[2][4];
        zero_frags(c);
        gemm3_acc(aHi, aLo, hf ? sWbHi : sWaHi, hf ? sWbLo : sWaLo, c, wm, wn);
#pragma unroll
        for (int i = 0; i < 2; ++i)
#pragma unroll
            for (int j = 0; j < 4; ++j)
                wmma::store_matrix_sync(
                    g_P + (size_t)(n0 + wm * 32 + i * 16) * 256 + hf * 128 + wn * 64 + j * 16,
                    c[i][j], 256, wmma::mem_row_major);
    }
}

// ---------------- persistent fused edge MLP + scatter (2-product wmma) ------
// smem: weights [0,139264) | A fp16 [139264,+34816) | staging f32 aliases A
//       [139264, 206848) | aux at 206848
#define SM_A    139264
#define SM_AUXE 206848
#define EDGE_SMEM (206848 + 2048 + 1024)

__global__ __launch_bounds__(256, 1)
void edge_persist_kernel(const float* __restrict__ ef,
                         const float* __restrict__ b1, const float* __restrict__ b2,
                         const int* __restrict__ src, const int* __restrict__ dst) {
    extern __shared__ char smraw[];
    char* base = (char*)(((uintptr_t)smraw + 1023) & ~(uintptr_t)1023);

    half* sWcHi = (half*)(base + 0);
    half* sWcLo = (half*)(base + 34816);
    half* sW2Hi = (half*)(base + 69632);
    half* sW2Lo = (half*)(base + 104448);
    half* sA    = (half*)(base + SM_A);
    float* stg  = (float*)(base + SM_A);      // aliases A
    int*   sSrc = (int*)(base + SM_AUXE + 0);
    int*   sDst = (int*)(base + SM_AUXE + 512);
    float* sB1  = (float*)(base + SM_AUXE + 1024);
    float* sB2  = (float*)(base + SM_AUXE + 1536);

    const int tid = threadIdx.x;
    const int wid = tid >> 5;
    const int wm = wid & 3;
    const int wn = wid >> 2;
    const int row = tid >> 1;
    const int c0 = (tid & 1) * 64;

    copy_tile(sWcHi, g_WcHi, tid);
    copy_tile(sWcLo, g_WcLo, tid);
    copy_tile(sW2Hi, g_W2Hi, tid);
    copy_tile(sW2Lo, g_W2Lo, tid);
    if (tid < 128) { sB1[tid] = b1[tid]; sB2[tid] = b2[tid]; }

    const int NT = N_EDGES / 128;  // 5000
    for (int t = blockIdx.x; t < NT; t += gridDim.x) {
        const int e0 = t * 128;
        __syncthreads();   // prev tile's staging/sSrc fully consumed

        // indices + L2 prefetch of P gather rows
        if (tid < 128) {
            int s = src[e0 + tid], d = dst[e0 + tid];
            sSrc[tid] = s;
            sDst[tid] = d;
            const char* pa = (const char*)(g_P + (size_t)s * 256);
            const char* pb = (const char*)(g_P + (size_t)d * 256 + 128);
#pragma unroll
            for (int q = 0; q < 4; ++q) {
                asm volatile("prefetch.global.L2 [%0];" :: "l"(pa + q * 128));
                asm volatile("prefetch.global.L2 [%0];" :: "l"(pb + q * 128));
            }
        }

        // A tile: ef rows -> single fp16
        {
            const float4* srcp = (const float4*)(ef + (size_t)(e0 + row) * 128 + c0);
            half* dh = sA + row * KP + c0;
#pragma unroll
            for (int g = 0; g < 16; ++g) {
                float4 v = srcp[g];
                *(uint2*)(dh + g * 4) =
                    make_uint2(pack_h2(__float2half_rn(v.x), __float2half_rn(v.y)),
                               pack_h2(__float2half_rn(v.z), __float2half_rn(v.w)));
            }
        }
        // prefetch next tile's ef into L2 while GEMMs run
        {
            int nt2 = t + gridDim.x;
            if (nt2 < NT) {
                const char* nef = (const char*)ef + (size_t)nt2 * 128 * 512;
                asm volatile("prefetch.global.L2 [%0];" :: "l"(nef + tid * 256));
                asm volatile("prefetch.global.L2 [%0];" :: "l"(nef + tid * 256 + 128));
            }
        }
        __syncthreads();

        // ---- GEMM1: stg = ef @ Wc ----
        FragC c[2][4];
        zero_frags(c);
        gemm2p_acc(sA, sWcHi, sWcLo, c, wm, wn);
        __syncthreads();           // all warps done reading A (stg aliases A)
        store_stage(c, stg, wm, wn);
        __syncthreads();

        // ---- epilogue 1: m1 = silu(stg + Pa[src] + Pb[dst] + b1) -> sA fp16
        float xs[64];
        {
            const float* st = stg + row * SP + c0;
#pragma unroll
            for (int g = 0; g < 16; ++g) {
                float4 v = *(const float4*)(st + g * 4);
                xs[g * 4 + 0] = v.x; xs[g * 4 + 1] = v.y;
                xs[g * 4 + 2] = v.z; xs[g * 4 + 3] = v.w;
            }
        }
        __syncthreads();           // all staging reads complete before overwrite
        {
            const int s = sSrc[row], dn = sDst[row];
            const float* pa = g_P + (size_t)s * 256 + c0;
            const float* pb = g_P + (size_t)dn * 256 + 128 + c0;
            half* dh = sA + row * KP + c0;
#pragma unroll
            for (int g = 0; g < 16; ++g) {
                float4 A = *(const float4*)(pa + g * 4);
                float4 B = *(const float4*)(pb + g * 4);
                int cc = c0 + g * 4;
                float x0 = silu_f(xs[g * 4 + 0] + A.x + B.x + sB1[cc + 0]);
                float x1 = silu_f(xs[g * 4 + 1] + A.y + B.y + sB1[cc + 1]);
                float x2 = silu_f(xs[g * 4 + 2] + A.z + B.z + sB1[cc + 2]);
                float x3 = silu_f(xs[g * 4 + 3] + A.w + B.w + sB1[cc + 3]);
                *(uint2*)(dh + g * 4) =
                    make_uint2(pack_h2(__float2half_rn(x0), __float2half_rn(x1)),
                               pack_h2(__float2half_rn(x2), __float2half_rn(x3)));
            }
        }
        __syncthreads();

        // ---- GEMM2: stg = m1 @ W2 ----
        zero_frags(c);
        gemm2p_acc(sA, sW2Hi, sW2Lo, c, wm, wn);
        __syncthreads();
        store_stage(c, stg, wm, wn);
        __syncthreads();

        // ---- epilogue 2: scatter-add silu(stg + b2) into g_msum[src] ----
        {
            const int s = sSrc[row];
            const float* st = stg + row * SP + c0;
            float* outp = g_msum + (size_t)s * 128 + c0;
#pragma unroll
            for (int g = 0; g < 16; ++g) {
                float4 v = *(const float4*)(st + g * 4);
                int cc = c0 + g * 4;
                red_add4(outp + g * 4,
                         silu_f(v.x + sB2[cc + 0]), silu_f(v.y + sB2[cc + 1]),
                         silu_f(v.z + sB2[cc + 2]), silu_f(v.w + sB2[cc + 3]));
            }
        }
    }
}

// ---------------- kernel: aggregation MLP + residual (wmma 3-split) ---------
// smem: 4 weight tiles [0,139264) | A hi/lo [139264..208896) | staging aliases
//       A [139264,206848) | aux at 208896
#define AGG_SMEM (208896 + 1024 + 1024)
__global__ __launch_bounds__(256, 1)
void agg_kernel(const float* __restrict__ nf,
                const float* __restrict__ ab1, const float* __restrict__ ab2,
                float* __restrict__ out) {
    extern __shared__ char smraw[];
    char* base = (char*)(((uintptr_t)smraw + 1023) & ~(uintptr_t)1023);
    half* T0  = (half*)(base + 0);
    half* T1  = (half*)(base + 34816);
    half* T2  = (half*)(base + 69632);
    half* T3  = (half*)(base + 104448);
    half* aHi = (half*)(base + 139264);
    half* aLo = (half*)(base + 174080);
    float* stg = (float*)(base + 139264);     // aliases A hi/lo
    float* sB1 = (float*)(base + 208896);
    float* sB2 = (float*)(base + 209408);

    const int tid = threadIdx.x;
    const int wid = tid >> 5;
    const int wm = wid & 3;
    const int wn = wid >> 2;
    const int row = tid >> 1;
    const int c0 = (tid & 1) * 64;
    const int n0 = blockIdx.x * 128;

    copy_tile(T0, g_A1aHi, tid);
    copy_tile(T1, g_A1aLo, tid);
    copy_tile(T2, g_A1bHi, tid);
    copy_tile(T3, g_A1bLo, tid);
    if (tid < 128) { sB1[tid] = ab1[tid]; sB2[tid] = ab2[tid]; }

    // A = h tile (padded: no bounds checks)
    {
        const float4* srcp = (const float4*)(g_h + (size_t)(n0 + row) * 128 + c0);
        half* dh = aHi + row * KP + c0;
        half* dl = aLo + row * KP + c0;
#pragma unroll
        for (int g = 0; g < 16; ++g) {
            float4 v = srcp[g];
            half h0, l0, h1, l1, h2, l2, h3, l3;
            split_h(v.x, h0, l0); split_h(v.y, h1, l1);
            split_h(v.z, h2, l2); split_h(v.w, h3, l3);
            *(uint2*)(dh + g * 4) = make_uint2(pack_h2(h0, h1), pack_h2(h2, h3));
            *(uint2*)(dl + g * 4) = make_uint2(pack_h2(l0, l1), pack_h2(l2, l3));
        }
    }
    __syncthreads();

    FragC c[2][4];
    zero_frags(c);
    gemm3_acc(aHi, aLo, T0, T1, c, wm, wn);     // h @ agg_w1[:128]
    __syncthreads();                            // done reading A

    // A = mean tile
    {
        float inv = 1.0f / fmaxf(g_cnt[n0 + row], 1.0f);
        const float4* srcp = (const float4*)(g_msum + (size_t)(n0 + row) * 128 + c0);
        half* dh = aHi + row * KP + c0;
        half* dl = aLo + row * KP + c0;
#pragma unroll
        for (int g = 0; g < 16; ++g) {
            float4 v = srcp[g];
            v.x *= inv; v.y *= inv; v.z *= inv; v.w *= inv;
            half h0, l0, h1, l1, h2, l2, h3, l3;
            split_h(v.x, h0, l0); split_h(v.y, h1, l1);
            split_h(v.z, h2, l2); split_h(v.w, h3, l3);
            *(uint2*)(dh + g * 4) = make_uint2(pack_h2(h0, h1), pack_h2(h2, h3));
            *(uint2*)(dl + g * 4) = make_uint2(pack_h2(l0, l1), pack_h2(l2, l3));
        }
    }
    __syncthreads();
    gemm3_acc(aHi, aLo, T2, T3, c, wm, wn);     // += mean @ agg_w1[128:]
    __syncthreads();                            // done reading A + T0/T1 long ago

    store_stage(c, stg, wm, wn);
    copy_tile(T0, g_A2Hi, tid);                 // overwrite with agg_w2
    copy_tile(T1, g_A2Lo, tid);
    __syncthreads();

    // epilogue 1: m1 = silu(stg + ab1) -> A hi/lo (aliases stg: read-all first)
    float xs[64];
    {
        const float* st = stg + row * SP + c0;
#pragma unroll
        for (int g = 0; g < 16; ++g) {
            float4 v = *(const float4*)(st + g * 4);
            xs[g * 4 + 0] = v.x; xs[g * 4 + 1] = v.y;
            xs[g * 4 + 2] = v.z; xs[g * 4 + 3] = v.w;
        }
    }
    __syncthreads();
    {
        half* dh = aHi + row * KP + c0;
        half* dl = aLo + row * KP + c0;
#pragma unroll
        for (int g = 0; g < 16; ++g) {
            int cc = c0 + g * 4;
            float x0 = silu_f(xs[g * 4 + 0] + sB1[cc + 0]);
            float x1 = silu_f(xs[g * 4 + 1] + sB1[cc + 1]);
            float x2 = silu_f(xs[g * 4 + 2] + sB1[cc + 2]);
            float x3 = silu_f(xs[g * 4 + 3] + sB1[cc + 3]);
            half h0, l0, h1, l1, h2, l2, h3, l3;
            split_h(x0, h0, l0); split_h(x1, h1, l1);
            split_h(x2, h2, l2); split_h(x3, h3, l3);
            *(uint2*)(dh + g * 4) = make_uint2(pack_h2(h0, h1), pack_h2(h2, h3));
            *(uint2*)(dl + g * 4) = make_uint2(pack_h2(l0, l1), pack_h2(l2, l3));
        }
    }
    __syncthreads();

    zero_frags(c);
    gemm3_acc(aHi, aLo, T0, T1, c, wm, wn);     // m1 @ agg_w2
    __syncthreads();
    store_stage(c, stg, wm, wn);
    __syncthreads();

    // epilogue 2: out = nf + silu(stg + ab2)
    {
        int n = n0 + row;
        if (n < N_NODES) {
            const float* st = stg + row * SP + c0;
            const float* nfp = nf + (size_t)n * 128 + c0;
            float* o = out + (size_t)n * 128 + c0;
#pragma unroll
            for (int g = 0; g < 16; ++g) {
                float4 v = *(const float4*)(st + g * 4);
                float4 f = *(const float4*)(nfp + g * 4);
                int cc = c0 + g * 4;
                float4 r;
                r.x = f.x + silu_f(v.x + sB2[cc + 0]);
                r.y = f.y + silu_f(v.y + sB2[cc + 1]);
                r.z = f.z + silu_f(v.z + sB2[cc + 2]);
                r.w = f.w + silu_f(v.w + sB2[cc + 3]);
                *(float4*)(o + g * 4) = r;
            }
        }
    }
}

// ---------------- launcher ----------------
extern "C" void kernel_launch(void* const* d_in, const int* in_sizes, int n_in,
                              void* d_out, int out_size) {
    (void)in_sizes; (void)n_in; (void)out_size;
    const float* nf  = (const float*)d_in[0];
    const float* ef  = (const float*)d_in[1];
    const float* gam = (const float*)d_in[2];
    const float* bet = (const float*)d_in[3];
    const float* mw1 = (const float*)d_in[4];
    const float* mb1 = (const float*)d_in[5];
    const float* mw2 = (const float*)d_in[6];
    const float* mb2 = (const float*)d_in[7];
    const float* aw1 = (const float*)d_in[8];
    const float* ab1 = (const float*)d_in[9];
    const float* aw2 = (const float*)d_in[10];
    const float* ab2 = (const float*)d_in[11];
    const int* eidx  = (const int*)d_in[12];
    const int* src = eidx;
    const int* dst = eidx + N_EDGES;
    float* out = (float*)d_out;

    cudaFuncSetAttribute(edge_persist_kernel, cudaFuncAttributeMaxDynamicSharedMemorySize, EDGE_SMEM);
    cudaFuncSetAttribute(agg_kernel,   cudaFuncAttributeMaxDynamicSharedMemorySize, AGG_SMEM);
    cudaFuncSetAttribute(pnode_kernel, cudaFuncAttributeMaxDynamicSharedMemorySize, PNODE_SMEM);

    const int NODE_TILES = NPAD / 128;  // 313

    zero_kernel<<<(NPAD * D / 4 + 255) / 256, 256>>>();
    ln_kernel<<<N_NODES / 8, 256>>>(nf, gam, bet);
    wprep_kernel<<<448, 256>>>(mw1, mw2, aw1, aw2);
    pnode_kernel<<<NODE_TILES, 256, PNODE_SMEM>>>();
    cnt_kernel<<<(N_EDGES + 255) / 256, 256>>>(src);
    edge_persist_kernel<<<152, 256, EDGE_SMEM>>>(ef, mb1, mb2, src, dst);
    agg_kernel<<<NODE_TILES, 256, AGG_SMEM>>>(nf, ab1, ab2, out);
}

// round 10
// speedup vs baseline: 1.2200x; 1.2200x over previous
#include <cuda_runtime.h>
#include <cuda_fp16.h>
#include <mma.h>
#include <cstdint>

using namespace nvcuda;

// Problem constants
#define N_NODES 40000
#define NPAD    40064
#define N_EDGES 640000
#define D 128

#define KP 136           // half elements per row in A/W tiles (pad 8)
#define SP 132           // float elements per row in staging

// ---------------- device scratch ----------------
__device__ float g_h[NPAD * D];
__device__ float g_P[NPAD * 2 * D];
__device__ float g_msum[NPAD * D];
__device__ float g_cnt[NPAD];

// fp16 weight tiles, [n][KP] (B col-major for wmma). single-precision fp16:
__device__ __align__(32) half g_W1c[128 * KP];    // msg_w1 rows [256,384)
__device__ __align__(32) half g_W2[128 * KP];     // msg_w2
__device__ __align__(32) half g_Wa[128 * KP];     // msg_w1 rows [0,128)
__device__ __align__(32) half g_Wb[128 * KP];     // msg_w1 rows [128,256)
// split hi/lo (agg keeps 3-product accuracy):
__device__ __align__(32) half g_A1aHi[128 * KP];
__device__ __align__(32) half g_A1aLo[128 * KP];
__device__ __align__(32) half g_A1bHi[128 * KP];
__device__ __align__(32) half g_A1bLo[128 * KP];
__device__ __align__(32) half g_A2Hi[128 * KP];
__device__ __align__(32) half g_A2Lo[128 * KP];

// ---------------- helpers ----------------
__device__ __forceinline__ float silu_f(float x) {
    return x / (1.0f + __expf(-x));
}

__device__ __forceinline__ void red_add4(float* p, float a, float b, float c, float d) {
    asm volatile("red.global.add.v4.f32 [%0], {%1, %2, %3, %4};"
                 :: "l"(p), "f"(a), "f"(b), "f"(c), "f"(d) : "memory");
}

__device__ __forceinline__ void split_h(float x, half &h, half &l) {
    h = __float2half_rn(x);
    l = __float2half_rn(x - __half2float(h));
}

__device__ __forceinline__ uint32_t pack_h2(half a, half b) {
    __half2 t = __halves2half2(a, b);
    return *reinterpret_cast<uint32_t*>(&t);
}

typedef wmma::fragment<wmma::accumulator, 16, 16, 16, float> FragC;
typedef wmma::fragment<wmma::matrix_a, 16, 16, 16, half, wmma::row_major> FragA;
typedef wmma::fragment<wmma::matrix_b, 16, 16, 16, half, wmma::col_major> FragB;

// single-product 32x32-per-warp (16 warps cover 128x128)
__device__ __forceinline__ void gemm1p_512(const half* __restrict__ aH,
                                           const half* __restrict__ bW,
                                           FragC c[2][2], int wm, int wn) {
#pragma unroll
    for (int ks = 0; ks < 8; ++ks) {
        const int k0 = ks * 16;
        FragA ah[2];
#pragma unroll
        for (int i = 0; i < 2; ++i)
            wmma::load_matrix_sync(ah[i], aH + (wm * 32 + i * 16) * KP + k0, KP);
#pragma unroll
        for (int j = 0; j < 2; ++j) {
            FragB b;
            wmma::load_matrix_sync(b, bW + (wn * 32 + j * 16) * KP + k0, KP);
#pragma unroll
            for (int i = 0; i < 2; ++i)
                wmma::mma_sync(c[i][j], ah[i], b, c[i][j]);
        }
    }
}

// single-product 32x64-per-warp (8 warps cover 128x128)
__device__ __forceinline__ void gemm1p_256(const half* __restrict__ aH,
                                           const half* __restrict__ bW,
                                           FragC c[2][4], int wm, int wn) {
#pragma unroll
    for (int ks = 0; ks < 8; ++ks) {
        const int k0 = ks * 16;
        FragA ah[2];
#pragma unroll
        for (int i = 0; i < 2; ++i)
            wmma::load_matrix_sync(ah[i], aH + (wm * 32 + i * 16) * KP + k0, KP);
#pragma unroll
        for (int j = 0; j < 4; ++j) {
            FragB b;
            wmma::load_matrix_sync(b, bW + (wn * 64 + j * 16) * KP + k0, KP);
#pragma unroll
            for (int i = 0; i < 2; ++i)
                wmma::mma_sync(c[i][j], ah[i], b, c[i][j]);
        }
    }
}

// 3-product (agg): c += Ahi*Bhi + Alo*Bhi + Ahi*Blo
__device__ __forceinline__ void gemm3_acc(const half* __restrict__ aHi,
                                          const half* __restrict__ aLo,
                                          const half* __restrict__ bHi,
                                          const half* __restrict__ bLo,
                                          FragC c[2][4], int wm, int wn) {
#pragma unroll
    for (int ks = 0; ks < 8; ++ks) {
        const int k0 = ks * 16;
        FragA ah[2], al[2];
#pragma unroll
        for (int i = 0; i < 2; ++i) {
            const int m0 = wm * 32 + i * 16;
            wmma::load_matrix_sync(ah[i], aHi + m0 * KP + k0, KP);
            wmma::load_matrix_sync(al[i], aLo + m0 * KP + k0, KP);
        }
#pragma unroll
        for (int j = 0; j < 4; ++j) {
            const int n0 = wn * 64 + j * 16;
            FragB bh, bl;
            wmma::load_matrix_sync(bh, bHi + n0 * KP + k0, KP);
            wmma::load_matrix_sync(bl, bLo + n0 * KP + k0, KP);
#pragma unroll
            for (int i = 0; i < 2; ++i) {
                wmma::mma_sync(c[i][j], ah[i], bh, c[i][j]);
                wmma::mma_sync(c[i][j], al[i], bh, c[i][j]);
                wmma::mma_sync(c[i][j], ah[i], bl, c[i][j]);
            }
        }
    }
}

// copy one 34816B weight tile global->smem
template <int NTHR>
__device__ __forceinline__ void copy_tile(half* dst, const half* src, int tid) {
    uint4* d = (uint4*)dst;
    const uint4* s = (const uint4*)src;
    for (int idx = tid; idx < 2176; idx += NTHR) d[idx] = s[idx];
}

// ---------------- kernel: zero scratch (+ pad rows of g_h) ----------------
__global__ void zero_kernel() {
    int i = blockIdx.x * blockDim.x + threadIdx.x;
    const int total4 = NPAD * D / 4;
    if (i < total4) reinterpret_cast<float4*>(g_msum)[i] = make_float4(0.f, 0.f, 0.f, 0.f);
    if (i < NPAD) g_cnt[i] = 0.0f;
    if (i < (NPAD - N_NODES) * D / 4)
        reinterpret_cast<float4*>(g_h + N_NODES * D)[i] = make_float4(0.f, 0.f, 0.f, 0.f);
}

// ---------------- kernel: LayerNorm ----------------
__global__ void ln_kernel(const float* __restrict__ x,
                          const float* __restrict__ gamma,
                          const float* __restrict__ beta) {
    int warp = threadIdx.x >> 5;
    int lane = threadIdx.x & 31;
    int n = blockIdx.x * 8 + warp;
    float4 v = *reinterpret_cast<const float4*>(x + (size_t)n * D + lane * 4);
    float s = v.x + v.y + v.z + v.w;
#pragma unroll
    for (int o = 16; o > 0; o >>= 1) s += __shfl_xor_sync(0xffffffffu, s, o);
    float mu = s * (1.0f / D);
    float d0 = v.x - mu, d1 = v.y - mu, d2 = v.z - mu, d3 = v.w - mu;
    float ss = d0 * d0 + d1 * d1 + d2 * d2 + d3 * d3;
#pragma unroll
    for (int o = 16; o > 0; o >>= 1) ss += __shfl_xor_sync(0xffffffffu, ss, o);
    float rs = rsqrtf(ss * (1.0f / D) + 1e-5f);
    float4 g = *reinterpret_cast<const float4*>(gamma + lane * 4);
    float4 b = *reinterpret_cast<const float4*>(beta + lane * 4);
    float4 o4;
    o4.x = d0 * rs * g.x + b.x;
    o4.y = d1 * rs * g.y + b.y;
    o4.z = d2 * rs * g.z + b.z;
    o4.w = d3 * rs * g.w + b.w;
    *reinterpret_cast<float4*>(g_h + (size_t)n * D + lane * 4) = o4;
}

// ---------------- kernel: per-src edge counts ----------------
__global__ void cnt_kernel(const int* __restrict__ src) {
    int i = blockIdx.x * blockDim.x + threadIdx.x;
    if (i < N_EDGES) atomicAdd(&g_cnt[src[i]], 1.0f);
}

// ---------------- kernel: weight prep ----------------
// mats 0..3 single fp16 (edge/pnode), 4..6 split hi/lo (agg)
__global__ void wprep_kernel(const float* __restrict__ mw1, const float* __restrict__ mw2,
                             const float* __restrict__ aw1, const float* __restrict__ aw2) {
    int i = blockIdx.x * blockDim.x + threadIdx.x;
    if (i >= 7 * 16384) return;
    int mat = i >> 14;
    int r = i & 16383;
    int n = r >> 7;
    int k = r & 127;
    int off = n * KP + k;
    switch (mat) {
        case 0: g_W1c[off] = __float2half_rn(mw1[(256 + k) * 128 + n]); break;
        case 1: g_W2[off]  = __float2half_rn(mw2[k * 128 + n]);         break;
        case 2: g_Wa[off]  = __float2half_rn(mw1[k * 128 + n]);         break;
        case 3: g_Wb[off]  = __float2half_rn(mw1[(128 + k) * 128 + n]); break;
        case 4: { half h, l; split_h(aw1[k * 128 + n], h, l);
                  g_A1aHi[off] = h; g_A1aLo[off] = l; } break;
        case 5: { half h, l; split_h(aw1[(128 + k) * 128 + n], h, l);
                  g_A1bHi[off] = h; g_A1bLo[off] = l; } break;
        default: { half h, l; split_h(aw2[k * 128 + n], h, l);
                  g_A2Hi[off] = h; g_A2Lo[off] = l; } break;
    }
}

// ---------------- kernel: node projections P = h @ [Wa|Wb], single fp16 -----
// smem: Wa 34816 | Wb 34816 | A 34816 = 104448
#define PNODE_SMEM (104448 + 1024)
__global__ __launch_bounds__(256, 2)
void pnode_kernel() {
    extern __shared__ char smraw[];
    char* base = (char*)(((uintptr_t)smraw + 255) & ~(uintptr_t)255);
    half* sWa = (half*)(base + 0);
    half* sWb = (half*)(base + 34816);
    half* sA  = (half*)(base + 69632);

    const int tid = threadIdx.x;
    const int wid = tid >> 5;
    const int wm = wid & 3;
    const int wn = wid >> 2;
    const int row = tid >> 1;
    const int c0 = (tid & 1) * 64;
    const int n0 = blockIdx.x * 128;

    copy_tile<256>(sWa, g_Wa, tid);
    copy_tile<256>(sWb, g_Wb, tid);

    // A = h tile, single fp16 (padded globals)
    {
        const float4* srcp = (const float4*)(g_h + (size_t)(n0 + row) * 128 + c0);
        half* dh = sA + row * KP + c0;
#pragma unroll
        for (int g = 0; g < 16; ++g) {
            float4 v = srcp[g];
            *(uint2*)(dh + g * 4) =
                make_uint2(pack_h2(__float2half_rn(v.x), __float2half_rn(v.y)),
                           pack_h2(__float2half_rn(v.z), __float2half_rn(v.w)));
        }
    }
    __syncthreads();

#pragma unroll
    for (int hf = 0; hf < 2; ++hf) {
        FragC c[2][4];
#pragma unroll
        for (int i = 0; i < 2; ++i)
#pragma unroll
            for (int j = 0; j < 4; ++j) wmma::fill_fragment(c[i][j], 0.0f);
        gemm1p_256(sA, hf ? sWb : sWa, c, wm, wn);
#pragma unroll
        for (int i = 0; i < 2; ++i)
#pragma unroll
            for (int j = 0; j < 4; ++j)
                wmma::store_matrix_sync(
                    g_P + (size_t)(n0 + wm * 32 + i * 16) * 256 + hf * 128 + wn * 64 + j * 16,
                    c[i][j], 256, wmma::mem_row_major);
    }
}

// ---------------- persistent edge MLP + scatter (single fp16, de-aliased) ---
// smem: W1c 0 | W2 34816 | A 69632 | M1 104448 | stg 139264 (67584) | aux 206848
#define SM_EW1  0
#define SM_EW2  34816
#define SM_EA   69632
#define SM_EM1  104448
#define SM_ESTG 139264
#define SM_EAUX 206848
#define EDGE_SMEM (206848 + 1024 + 1024)

__global__ __launch_bounds__(512, 1)
void edge_persist_kernel(const float* __restrict__ ef,
                         const float* __restrict__ b1, const float* __restrict__ b2,
                         const int* __restrict__ src, const int* __restrict__ dst) {
    extern __shared__ char smraw[];
    char* base = (char*)(((uintptr_t)smraw + 1023) & ~(uintptr_t)1023);

    half* sW1  = (half*)(base + SM_EW1);
    half* sW2  = (half*)(base + SM_EW2);
    half* sA   = (half*)(base + SM_EA);
    half* sM1  = (half*)(base + SM_EM1);
    float* stg = (float*)(base + SM_ESTG);
    float* sB1 = (float*)(base + SM_EAUX);
    float* sB2 = (float*)(base + SM_EAUX + 512);

    const int tid = threadIdx.x;
    const int wid = tid >> 5;
    const int wm = wid & 3;      // 4 row groups of 32
    const int wn = wid >> 2;     // 4 col groups of 32
    const int row = tid >> 2;    // 0..127
    const int c0 = (tid & 3) * 32;

    copy_tile<512>(sW1, g_W1c, tid);
    copy_tile<512>(sW2, g_W2, tid);
    if (tid < 128) { sB1[tid] = b1[tid]; sB2[tid] = b2[tid]; }

    const int NT = N_EDGES / 128;  // 5000
    for (int t = blockIdx.x; t < NT; t += gridDim.x) {
        const int e0 = t * 128;

        // A tile: ef rows -> fp16 (single); also prefetch P rows + next ef
        {
            const float4* srcp = (const float4*)(ef + (size_t)(e0 + row) * 128 + c0);
            half* dh = sA + row * KP + c0;
#pragma unroll
            for (int g = 0; g < 8; ++g) {
                float4 v = srcp[g];
                *(uint2*)(dh + g * 4) =
                    make_uint2(pack_h2(__float2half_rn(v.x), __float2half_rn(v.y)),
                               pack_h2(__float2half_rn(v.z), __float2half_rn(v.w)));
            }
        }
        if (tid < 128) {
            int s = src[e0 + tid], d = dst[e0 + tid];
            const char* pa = (const char*)(g_P + (size_t)s * 256);
            const char* pb = (const char*)(g_P + (size_t)d * 256 + 128);
#pragma unroll
            for (int q = 0; q < 4; ++q) {
                asm volatile("prefetch.global.L2 [%0];" :: "l"(pa + q * 128));
                asm volatile("prefetch.global.L2 [%0];" :: "l"(pb + q * 128));
            }
        }
        {
            int nt2 = t + gridDim.x;
            if (nt2 < NT) {
                const char* nef = (const char*)ef + (size_t)nt2 * 128 * 512;
                asm volatile("prefetch.global.L2 [%0];" :: "l"(nef + tid * 128));
            }
        }
        __syncthreads();   // #1: sA visible (also: prev scatter stg reads done)

        // ---- GEMM1: stg = ef @ W1c ----
        FragC c[2][2];
#pragma unroll
        for (int i = 0; i < 2; ++i)
#pragma unroll
            for (int j = 0; j < 2; ++j) wmma::fill_fragment(c[i][j], 0.0f);
        gemm1p_512(sA, sW1, c, wm, wn);
#pragma unroll
        for (int i = 0; i < 2; ++i)
#pragma unroll
            for (int j = 0; j < 2; ++j)
                wmma::store_matrix_sync(stg + (wm * 32 + i * 16) * SP + wn * 32 + j * 16,
                                        c[i][j], SP, wmma::mem_row_major);
        __syncthreads();   // #2: stg visible

        // ---- epilogue 1: m1 = silu(stg + Pa[src] + Pb[dst] + b1) -> sM1 ----
        {
            const int s = src[e0 + row], dn = dst[e0 + row];
            const float* pa = g_P + (size_t)s * 256 + c0;
            const float* pb = g_P + (size_t)dn * 256 + 128 + c0;
            const float* st = stg + row * SP + c0;
            half* dh = sM1 + row * KP + c0;
#pragma unroll
            for (int g = 0; g < 8; ++g) {
                float4 v = *(const float4*)(st + g * 4);
                float4 A = *(const float4*)(pa + g * 4);
                float4 B = *(const float4*)(pb + g * 4);
                int cc = c0 + g * 4;
                float x0 = silu_f(v.x + A.x + B.x + sB1[cc + 0]);
                float x1 = silu_f(v.y + A.y + B.y + sB1[cc + 1]);
                float x2 = silu_f(v.z + A.z + B.z + sB1[cc + 2]);
                float x3 = silu_f(v.w + A.w + B.w + sB1[cc + 3]);
                *(uint2*)(dh + g * 4) =
                    make_uint2(pack_h2(__float2half_rn(x0), __float2half_rn(x1)),
                               pack_h2(__float2half_rn(x2), __float2half_rn(x3)));
            }
        }
        __syncthreads();   // #3: sM1 visible, stg reads done

        // ---- GEMM2: stg = m1 @ W2 ----
#pragma unroll
        for (int i = 0; i < 2; ++i)
#pragma unroll
            for (int j = 0; j < 2; ++j) wmma::fill_fragment(c[i][j], 0.0f);
        gemm1p_512(sM1, sW2, c, wm, wn);
#pragma unroll
        for (int i = 0; i < 2; ++i)
#pragma unroll
            for (int j = 0; j < 2; ++j)
                wmma::store_matrix_sync(stg + (wm * 32 + i * 16) * SP + wn * 32 + j * 16,
                                        c[i][j], SP, wmma::mem_row_major);
        __syncthreads();   // #4: stg visible

        // ---- epilogue 2: scatter-add silu(stg + b2) into g_msum[src] ----
        {
            const int s = src[e0 + row];
            const float* st = stg + row * SP + c0;
            float* outp = g_msum + (size_t)s * 128 + c0;
#pragma unroll
            for (int g = 0; g < 8; ++g) {
                float4 v = *(const float4*)(st + g * 4);
                int cc = c0 + g * 4;
                red_add4(outp + g * 4,
                         silu_f(v.x + sB2[cc + 0]), silu_f(v.y + sB2[cc + 1]),
                         silu_f(v.z + sB2[cc + 2]), silu_f(v.w + sB2[cc + 3]));
            }
        }
    }
}

// ---------------- kernel: aggregation MLP + residual (3-split, known-good) --
#define AGG_SMEM (208896 + 1024 + 1024)
__global__ __launch_bounds__(256, 1)
void agg_kernel(const float* __restrict__ nf,
                const float* __restrict__ ab1, const float* __restrict__ ab2,
                float* __restrict__ out) {
    extern __shared__ char smraw[];
    char* base = (char*)(((uintptr_t)smraw + 1023) & ~(uintptr_t)1023);
    half* T0  = (half*)(base + 0);
    half* T1  = (half*)(base + 34816);
    half* T2  = (half*)(base + 69632);
    half* T3  = (half*)(base + 104448);
    half* aHi = (half*)(base + 139264);
    half* aLo = (half*)(base + 174080);
    float* stg = (float*)(base + 139264);     // aliases A hi/lo
    float* sB1 = (float*)(base + 208896);
    float* sB2 = (float*)(base + 209408);

    const int tid = threadIdx.x;
    const int wid = tid >> 5;
    const int wm = wid & 3;
    const int wn = wid >> 2;
    const int row = tid >> 1;
    const int c0 = (tid & 1) * 64;
    const int n0 = blockIdx.x * 128;

    copy_tile<256>(T0, g_A1aHi, tid);
    copy_tile<256>(T1, g_A1aLo, tid);
    copy_tile<256>(T2, g_A1bHi, tid);
    copy_tile<256>(T3, g_A1bLo, tid);
    if (tid < 128) { sB1[tid] = ab1[tid]; sB2[tid] = ab2[tid]; }

    {
        const float4* srcp = (const float4*)(g_h + (size_t)(n0 + row) * 128 + c0);
        half* dh = aHi + row * KP + c0;
        half* dl = aLo + row * KP + c0;
#pragma unroll
        for (int g = 0; g < 16; ++g) {
            float4 v = srcp[g];
            half h0, l0, h1, l1, h2, l2, h3, l3;
            split_h(v.x, h0, l0); split_h(v.y, h1, l1);
            split_h(v.z, h2, l2); split_h(v.w, h3, l3);
            *(uint2*)(dh + g * 4) = make_uint2(pack_h2(h0, h1), pack_h2(h2, h3));
            *(uint2*)(dl + g * 4) = make_uint2(pack_h2(l0, l1), pack_h2(l2, l3));
        }
    }
    __syncthreads();

    FragC c[2][4];
#pragma unroll
    for (int i = 0; i < 2; ++i)
#pragma unroll
        for (int j = 0; j < 4; ++j) wmma::fill_fragment(c[i][j], 0.0f);
    gemm3_acc(aHi, aLo, T0, T1, c, wm, wn);
    __syncthreads();

    {
        float inv = 1.0f / fmaxf(g_cnt[n0 + row], 1.0f);
        const float4* srcp = (const float4*)(g_msum + (size_t)(n0 + row) * 128 + c0);
        half* dh = aHi + row * KP + c0;
        half* dl = aLo + row * KP + c0;
#pragma unroll
        for (int g = 0; g < 16; ++g) {
            float4 v = srcp[g];
            v.x *= inv; v.y *= inv; v.z *= inv; v.w *= inv;
            half h0, l0, h1, l1, h2, l2, h3, l3;
            split_h(v.x, h0, l0); split_h(v.y, h1, l1);
            split_h(v.z, h2, l2); split_h(v.w, h3, l3);
            *(uint2*)(dh + g * 4) = make_uint2(pack_h2(h0, h1), pack_h2(h2, h3));
            *(uint2*)(dl + g * 4) = make_uint2(pack_h2(l0, l1), pack_h2(l2, l3));
        }
    }
    __syncthreads();
    gemm3_acc(aHi, aLo, T2, T3, c, wm, wn);
    __syncthreads();

#pragma unroll
    for (int i = 0; i < 2; ++i)
#pragma unroll
        for (int j = 0; j < 4; ++j)
            wmma::store_matrix_sync(stg + (wm * 32 + i * 16) * SP + wn * 64 + j * 16,
                                    c[i][j], SP, wmma::mem_row_major);
    copy_tile<256>(T0, g_A2Hi, tid);
    copy_tile<256>(T1, g_A2Lo, tid);
    __syncthreads();

    float xs[64];
    {
        const float* st = stg + row * SP + c0;
#pragma unroll
        for (int g = 0; g < 16; ++g) {
            float4 v = *(const float4*)(st + g * 4);
            xs[g * 4 + 0] = v.x; xs[g * 4 + 1] = v.y;
            xs[g * 4 + 2] = v.z; xs[g * 4 + 3] = v.w;
        }
    }
    __syncthreads();
    {
        half* dh = aHi + row * KP + c0;
        half* dl = aLo + row * KP + c0;
#pragma unroll
        for (int g = 0; g < 16; ++g) {
            int cc = c0 + g * 4;
            float x0 = silu_f(xs[g * 4 + 0] + sB1[cc + 0]);
            float x1 = silu_f(xs[g * 4 + 1] + sB1[cc + 1]);
            float x2 = silu_f(xs[g * 4 + 2] + sB1[cc + 2]);
            float x3 = silu_f(xs[g * 4 + 3] + sB1[cc + 3]);
            half h0, l0, h1, l1, h2, l2, h3, l3;
            split_h(x0, h0, l0); split_h(x1, h1, l1);
            split_h(x2, h2, l2); split_h(x3, h3, l3);
            *(uint2*)(dh + g * 4) = make_uint2(pack_h2(h0, h1), pack_h2(h2, h3));
            *(uint2*)(dl + g * 4) = make_uint2(pack_h2(l0, l1), pack_h2(l2, l3));
        }
    }
    __syncthreads();

#pragma unroll
    for (int i = 0; i < 2; ++i)
#pragma unroll
        for (int j = 0; j < 4; ++j) wmma::fill_fragment(c[i][j], 0.0f);
    gemm3_acc(aHi, aLo, T0, T1, c, wm, wn);
    __syncthreads();
#pragma unroll
    for (int i = 0; i < 2; ++i)
#pragma unroll
        for (int j = 0; j < 4; ++j)
            wmma::store_matrix_sync(stg + (wm * 32 + i * 16) * SP + wn * 64 + j * 16,
                                    c[i][j], SP, wmma::mem_row_major);
    __syncthreads();

    {
        int n = n0 + row;
        if (n < N_NODES) {
            const float* st = stg + row * SP + c0;
            const float* nfp = nf + (size_t)n * 128 + c0;
            float* o = out + (size_t)n * 128 + c0;
#pragma unroll
            for (int g = 0; g < 16; ++g) {
                float4 v = *(const float4*)(st + g * 4);
                float4 f = *(const float4*)(nfp + g * 4);
                int cc = c0 + g * 4;
                float4 r;
                r.x = f.x + silu_f(v.x + sB2[cc + 0]);
                r.y = f.y + silu_f(v.y + sB2[cc + 1]);
                r.z = f.z + silu_f(v.z + sB2[cc + 2]);
                r.w = f.w + silu_f(v.w + sB2[cc + 3]);
                *(float4*)(o + g * 4) = r;
            }
        }
    }
}

// ---------------- launcher ----------------
extern "C" void kernel_launch(void* const* d_in, const int* in_sizes, int n_in,
                              void* d_out, int out_size) {
    (void)in_sizes; (void)n_in; (void)out_size;
    const float* nf  = (const float*)d_in[0];
    const float* ef  = (const float*)d_in[1];
    const float* gam = (const float*)d_in[2];
    const float* bet = (const float*)d_in[3];
    const float* mw1 = (const float*)d_in[4];
    const float* mb1 = (const float*)d_in[5];
    const float* mw2 = (const float*)d_in[6];
    const float* mb2 = (const float*)d_in[7];
    const float* aw1 = (const float*)d_in[8];
    const float* ab1 = (const float*)d_in[9];
    const float* aw2 = (const float*)d_in[10];
    const float* ab2 = (const float*)d_in[11];
    const int* eidx  = (const int*)d_in[12];
    const int* src = eidx;
    const int* dst = eidx + N_EDGES;
    float* out = (float*)d_out;

    cudaFuncSetAttribute(edge_persist_kernel, cudaFuncAttributeMaxDynamicSharedMemorySize, EDGE_SMEM);
    cudaFuncSetAttribute(agg_kernel,   cudaFuncAttributeMaxDynamicSharedMemorySize, AGG_SMEM);
    cudaFuncSetAttribute(pnode_kernel, cudaFuncAttributeMaxDynamicSharedMemorySize, PNODE_SMEM);

    const int NODE_TILES = NPAD / 128;  // 313

    zero_kernel<<<(NPAD * D / 4 + 255) / 256, 256>>>();
    ln_kernel<<<N_NODES / 8, 256>>>(nf, gam, bet);
    wprep_kernel<<<448, 256>>>(mw1, mw2, aw1, aw2);
    pnode_kernel<<<NODE_TILES, 256, PNODE_SMEM>>>();
    cnt_kernel<<<(N_EDGES + 255) / 256, 256>>>(src);
    edge_persist_kernel<<<152, 512, EDGE_SMEM>>>(ef, mb1, mb2, src, dst);
    agg_kernel<<<NODE_TILES, 256, AGG_SMEM>>>(nf, ab1, ab2, out);
}

// round 12
// speedup vs baseline: 1.3109x; 1.0744x over previous
#include <cuda_runtime.h>
#include <cuda_fp16.h>
#include <mma.h>
#include <cstdint>

using namespace nvcuda;

// Problem constants
#define N_NODES 40000
#define NPAD    40064
#define N_EDGES 640000
#define D 128

#define KP 136           // half elements per row in A/W tiles (pad 8)
#define SP 132           // float elements per row in staging

// ---------------- device scratch ----------------
__device__ float g_h[NPAD * D];
__device__ float g_P[NPAD * 2 * D];
__device__ float g_msum[NPAD * D];
__device__ float g_cnt[NPAD];

// fp16 weight tiles, [n][KP] (B col-major for wmma), single fp16.
__device__ __align__(32) half g_W1c[128 * KP];    // msg_w1 rows [256,384)
__device__ __align__(32) half g_W2[128 * KP];     // msg_w2
__device__ __align__(32) half g_Wa[128 * KP];     // msg_w1 rows [0,128)
__device__ __align__(32) half g_Wb[128 * KP];     // msg_w1 rows [128,256)
__device__ __align__(32) half g_A1a[128 * KP];    // agg_w1 rows [0,128)
__device__ __align__(32) half g_A1b[128 * KP];    // agg_w1 rows [128,256)
__device__ __align__(32) half g_A2[128 * KP];     // agg_w2

// ---------------- helpers ----------------
// silu(x) = x * sigmoid(x) = 0.5x * tanh(x/2) + 0.5x   (HW tanh, 1 SFU op)
__device__ __forceinline__ float silu_f(float x) {
    float t;
    asm("tanh.approx.f32 %0, %1;" : "=f"(t) : "f"(x * 0.5f));
    return fmaf(0.5f * x, t, 0.5f * x);
}

__device__ __forceinline__ void red_add4(float* p, float a, float b, float c, float d) {
    asm volatile("red.global.add.v4.f32 [%0], {%1, %2, %3, %4};"
                 :: "l"(p), "f"(a), "f"(b), "f"(c), "f"(d) : "memory");
}

// packed fp32x2 -> fp16x2 conversion (single F2FP.PACK)
__device__ __forceinline__ uint32_t cvt2h(float a, float b) {
    __half2 t = __float22half2_rn(make_float2(a, b));
    return *reinterpret_cast<uint32_t*>(&t);
}

typedef wmma::fragment<wmma::accumulator, 16, 16, 16, float> FragC;
typedef wmma::fragment<wmma::matrix_a, 16, 16, 16, half, wmma::row_major> FragA;
typedef wmma::fragment<wmma::matrix_b, 16, 16, 16, half, wmma::col_major> FragB;

// single-product 32x32-per-warp (16 warps cover 128x128)
__device__ __forceinline__ void gemm1p_512(const half* __restrict__ aH,
                                           const half* __restrict__ bW,
                                           FragC c[2][2], int wm, int wn) {
#pragma unroll
    for (int ks = 0; ks < 8; ++ks) {
        const int k0 = ks * 16;
        FragA ah[2];
#pragma unroll
        for (int i = 0; i < 2; ++i)
            wmma::load_matrix_sync(ah[i], aH + (wm * 32 + i * 16) * KP + k0, KP);
#pragma unroll
        for (int j = 0; j < 2; ++j) {
            FragB b;
            wmma::load_matrix_sync(b, bW + (wn * 32 + j * 16) * KP + k0, KP);
#pragma unroll
            for (int i = 0; i < 2; ++i)
                wmma::mma_sync(c[i][j], ah[i], b, c[i][j]);
        }
    }
}

// single-product 32x64-per-warp (8 warps cover 128x128)
__device__ __forceinline__ void gemm1p_256(const half* __restrict__ aH,
                                           const half* __restrict__ bW,
                                           FragC c[2][4], int wm, int wn) {
#pragma unroll
    for (int ks = 0; ks < 8; ++ks) {
        const int k0 = ks * 16;
        FragA ah[2];
#pragma unroll
        for (int i = 0; i < 2; ++i)
            wmma::load_matrix_sync(ah[i], aH + (wm * 32 + i * 16) * KP + k0, KP);
#pragma unroll
        for (int j = 0; j < 4; ++j) {
            FragB b;
            wmma::load_matrix_sync(b, bW + (wn * 64 + j * 16) * KP + k0, KP);
#pragma unroll
            for (int i = 0; i < 2; ++i)
                wmma::mma_sync(c[i][j], ah[i], b, c[i][j]);
        }
    }
}

template <int NTHR>
__device__ __forceinline__ void copy_tile(half* dst, const half* src, int tid) {
    uint4* d = (uint4*)dst;
    const uint4* s = (const uint4*)src;
    for (int idx = tid; idx < 2176; idx += NTHR) d[idx] = s[idx];
}

// ---------------- kernel: zero scratch (+ pad rows of g_h) ----------------
__global__ void zero_kernel() {
    int i = blockIdx.x * blockDim.x + threadIdx.x;
    const int total4 = NPAD * D / 4;
    if (i < total4) reinterpret_cast<float4*>(g_msum)[i] = make_float4(0.f, 0.f, 0.f, 0.f);
    if (i < NPAD) g_cnt[i] = 0.0f;
    if (i < (NPAD - N_NODES) * D / 4)
        reinterpret_cast<float4*>(g_h + N_NODES * D)[i] = make_float4(0.f, 0.f, 0.f, 0.f);
}

// ---------------- kernel: LayerNorm ----------------
__global__ void ln_kernel(const float* __restrict__ x,
                          const float* __restrict__ gamma,
                          const float* __restrict__ beta) {
    int warp = threadIdx.x >> 5;
    int lane = threadIdx.x & 31;
    int n = blockIdx.x * 8 + warp;
    float4 v = *reinterpret_cast<const float4*>(x + (size_t)n * D + lane * 4);
    float s = v.x + v.y + v.z + v.w;
#pragma unroll
    for (int o = 16; o > 0; o >>= 1) s += __shfl_xor_sync(0xffffffffu, s, o);
    float mu = s * (1.0f / D);
    float d0 = v.x - mu, d1 = v.y - mu, d2 = v.z - mu, d3 = v.w - mu;
    float ss = d0 * d0 + d1 * d1 + d2 * d2 + d3 * d3;
#pragma unroll
    for (int o = 16; o > 0; o >>= 1) ss += __shfl_xor_sync(0xffffffffu, ss, o);
    float rs = rsqrtf(ss * (1.0f / D) + 1e-5f);
    float4 g = *reinterpret_cast<const float4*>(gamma + lane * 4);
    float4 b = *reinterpret_cast<const float4*>(beta + lane * 4);
    float4 o4;
    o4.x = d0 * rs * g.x + b.x;
    o4.y = d1 * rs * g.y + b.y;
    o4.z = d2 * rs * g.z + b.z;
    o4.w = d3 * rs * g.w + b.w;
    *reinterpret_cast<float4*>(g_h + (size_t)n * D + lane * 4) = o4;
}

// ---------------- kernel: per-src edge counts ----------------
__global__ void cnt_kernel(const int* __restrict__ src) {
    int i = blockIdx.x * blockDim.x + threadIdx.x;
    if (i < N_EDGES) atomicAdd(&g_cnt[src[i]], 1.0f);
}

// ---------------- kernel: weight prep (all single fp16) ----------------
__global__ void wprep_kernel(const float* __restrict__ mw1, const float* __restrict__ mw2,
                             const float* __restrict__ aw1, const float* __restrict__ aw2) {
    int i = blockIdx.x * blockDim.x + threadIdx.x;
    if (i >= 7 * 16384) return;
    int mat = i >> 14;
    int r = i & 16383;
    int n = r >> 7;
    int k = r & 127;
    int off = n * KP + k;
    switch (mat) {
        case 0: g_W1c[off] = __float2half_rn(mw1[(256 + k) * 128 + n]); break;
        case 1: g_W2[off]  = __float2half_rn(mw2[k * 128 + n]);         break;
        case 2: g_Wa[off]  = __float2half_rn(mw1[k * 128 + n]);         break;
        case 3: g_Wb[off]  = __float2half_rn(mw1[(128 + k) * 128 + n]); break;
        case 4: g_A1a[off] = __float2half_rn(aw1[k * 128 + n]);         break;
        case 5: g_A1b[off] = __float2half_rn(aw1[(128 + k) * 128 + n]); break;
        default: g_A2[off] = __float2half_rn(aw2[k * 128 + n]);         break;
    }
}

// ---------------- kernel: node projections P = h @ [Wa|Wb] ----------------
// smem: Wa 34816 | Wb 34816 | A 34816 = 104448
#define PNODE_SMEM (104448 + 1024)
__global__ __launch_bounds__(256, 2)
void pnode_kernel() {
    extern __shared__ char smraw[];
    char* base = (char*)(((uintptr_t)smraw + 255) & ~(uintptr_t)255);
    half* sWa = (half*)(base + 0);
    half* sWb = (half*)(base + 34816);
    half* sA  = (half*)(base + 69632);

    const int tid = threadIdx.x;
    const int wid = tid >> 5;
    const int wm = wid & 3;
    const int wn = wid >> 2;
    const int row = tid >> 1;
    const int c0 = (tid & 1) * 64;
    const int n0 = blockIdx.x * 128;

    copy_tile<256>(sWa, g_Wa, tid);
    copy_tile<256>(sWb, g_Wb, tid);

    {
        const float4* srcp = (const float4*)(g_h + (size_t)(n0 + row) * 128 + c0);
        half* dh = sA + row * KP + c0;
#pragma unroll
        for (int g = 0; g < 16; ++g) {
            float4 v = srcp[g];
            *(uint2*)(dh + g * 4) = make_uint2(cvt2h(v.x, v.y), cvt2h(v.z, v.w));
        }
    }
    __syncthreads();

#pragma unroll
    for (int hf = 0; hf < 2; ++hf) {
        FragC c[2][4];
#pragma unroll
        for (int i = 0; i < 2; ++i)
#pragma unroll
            for (int j = 0; j < 4; ++j) wmma::fill_fragment(c[i][j], 0.0f);
        gemm1p_256(sA, hf ? sWb : sWa, c, wm, wn);
#pragma unroll
        for (int i = 0; i < 2; ++i)
#pragma unroll
            for (int j = 0; j < 4; ++j)
                wmma::store_matrix_sync(
                    g_P + (size_t)(n0 + wm * 32 + i * 16) * 256 + hf * 128 + wn * 64 + j * 16,
                    c[i][j], 256, wmma::mem_row_major);
    }
}

// ---------------- persistent edge MLP + scatter (single fp16) ----------------
// smem: W1c 0 | W2 34816 | A 69632 | M1 104448 | stg 139264 (67584) | aux 206848
#define SM_EW1  0
#define SM_EW2  34816
#define SM_EA   69632
#define SM_EM1  104448
#define SM_ESTG 139264
#define SM_EAUX 206848
#define EDGE_SMEM (206848 + 1024 + 1024)

__global__ __launch_bounds__(512, 1)
void edge_persist_kernel(const float* __restrict__ ef,
                         const float* __restrict__ b1, const float* __restrict__ b2,
                         const int* __restrict__ src, const int* __restrict__ dst) {
    extern __shared__ char smraw[];
    char* base = (char*)(((uintptr_t)smraw + 1023) & ~(uintptr_t)1023);

    half* sW1  = (half*)(base + SM_EW1);
    half* sW2  = (half*)(base + SM_EW2);
    half* sA   = (half*)(base + SM_EA);
    half* sM1  = (half*)(base + SM_EM1);
    float* stg = (float*)(base + SM_ESTG);
    float* sB1 = (float*)(base + SM_EAUX);
    float* sB2 = (float*)(base + SM_EAUX + 512);

    const int tid = threadIdx.x;
    const int wid = tid >> 5;
    const int wm = wid & 3;
    const int wn = wid >> 2;
    const int row = tid >> 2;    // 0..127
    const int c0 = (tid & 3) * 32;

    copy_tile<512>(sW1, g_W1c, tid);
    copy_tile<512>(sW2, g_W2, tid);
    if (tid < 128) { sB1[tid] = b1[tid]; sB2[tid] = b2[tid]; }

    const int NT = N_EDGES / 128;  // 5000
    for (int t = blockIdx.x; t < NT; t += gridDim.x) {
        const int e0 = t * 128;

        // A tile: ef rows -> fp16; prefetch P rows + next ef
        {
            const float4* srcp = (const float4*)(ef + (size_t)(e0 + row) * 128 + c0);
            half* dh = sA + row * KP + c0;
#pragma unroll
            for (int g = 0; g < 8; ++g) {
                float4 v = srcp[g];
                *(uint2*)(dh + g * 4) = make_uint2(cvt2h(v.x, v.y), cvt2h(v.z, v.w));
            }
        }
        if (tid < 128) {
            int s = src[e0 + tid], d = dst[e0 + tid];
            const char* pa = (const char*)(g_P + (size_t)s * 256);
            const char* pb = (const char*)(g_P + (size_t)d * 256 + 128);
#pragma unroll
            for (int q = 0; q < 4; ++q) {
                asm volatile("prefetch.global.L2 [%0];" :: "l"(pa + q * 128));
                asm volatile("prefetch.global.L2 [%0];" :: "l"(pb + q * 128));
            }
        }
        {
            int nt2 = t + gridDim.x;
            if (nt2 < NT) {
                const char* nef = (const char*)ef + (size_t)nt2 * 128 * 512;
                asm volatile("prefetch.global.L2 [%0];" :: "l"(nef + tid * 128));
            }
        }
        __syncthreads();   // #1

        // ---- GEMM1: stg = ef @ W1c ----
        FragC c[2][2];
#pragma unroll
        for (int i = 0; i < 2; ++i)
#pragma unroll
            for (int j = 0; j < 2; ++j) wmma::fill_fragment(c[i][j], 0.0f);
        gemm1p_512(sA, sW1, c, wm, wn);
#pragma unroll
        for (int i = 0; i < 2; ++i)
#pragma unroll
            for (int j = 0; j < 2; ++j)
                wmma::store_matrix_sync(stg + (wm * 32 + i * 16) * SP + wn * 32 + j * 16,
                                        c[i][j], SP, wmma::mem_row_major);
        __syncthreads();   // #2

        // ---- epilogue 1: m1 = silu(stg + Pa[src] + Pb[dst] + b1) -> sM1 ----
        {
            const int s = src[e0 + row], dn = dst[e0 + row];
            const float* pa = g_P + (size_t)s * 256 + c0;
            const float* pb = g_P + (size_t)dn * 256 + 128 + c0;
            const float* st = stg + row * SP + c0;
            half* dh = sM1 + row * KP + c0;
#pragma unroll
            for (int g = 0; g < 8; ++g) {
                float4 v = *(const float4*)(st + g * 4);
                float4 A = *(const float4*)(pa + g * 4);
                float4 B = *(const float4*)(pb + g * 4);
                int cc = c0 + g * 4;
                float x0 = silu_f(v.x + A.x + B.x + sB1[cc + 0]);
                float x1 = silu_f(v.y + A.y + B.y + sB1[cc + 1]);
                float x2 = silu_f(v.z + A.z + B.z + sB1[cc + 2]);
                float x3 = silu_f(v.w + A.w + B.w + sB1[cc + 3]);
                *(uint2*)(dh + g * 4) = make_uint2(cvt2h(x0, x1), cvt2h(x2, x3));
            }
        }
        __syncthreads();   // #3

        // ---- GEMM2: stg = m1 @ W2 ----
#pragma unroll
        for (int i = 0; i < 2; ++i)
#pragma unroll
            for (int j = 0; j < 2; ++j) wmma::fill_fragment(c[i][j], 0.0f);
        gemm1p_512(sM1, sW2, c, wm, wn);
#pragma unroll
        for (int i = 0; i < 2; ++i)
#pragma unroll
            for (int j = 0; j < 2; ++j)
                wmma::store_matrix_sync(stg + (wm * 32 + i * 16) * SP + wn * 32 + j * 16,
                                        c[i][j], SP, wmma::mem_row_major);
        __syncthreads();   // #4

        // ---- epilogue 2: scatter-add silu(stg + b2) into g_msum[src] ----
        {
            const int s = src[e0 + row];
            const float* st = stg + row * SP + c0;
            float* outp = g_msum + (size_t)s * 128 + c0;
#pragma unroll
            for (int g = 0; g < 8; ++g) {
                float4 v = *(const float4*)(st + g * 4);
                int cc = c0 + g * 4;
                red_add4(outp + g * 4,
                         silu_f(v.x + sB2[cc + 0]), silu_f(v.y + sB2[cc + 1]),
                         silu_f(v.z + sB2[cc + 2]), silu_f(v.w + sB2[cc + 3]));
            }
        }
    }
}

// ---------------- kernel: aggregation MLP + residual (single fp16) ----------
// smem: T0 0 | T1 34816 | A 69632 | stg 104448 (67584) | aux 172032
#define AGG_SMEM (172032 + 1024 + 1024)
__global__ __launch_bounds__(256, 1)
void agg_kernel(const float* __restrict__ nf,
                const float* __restrict__ ab1, const float* __restrict__ ab2,
                float* __restrict__ out) {
    extern __shared__ char smraw[];
    char* base = (char*)(((uintptr_t)smraw + 1023) & ~(uintptr_t)1023);
    half* T0  = (half*)(base + 0);
    half* T1  = (half*)(base + 34816);
    half* sA  = (half*)(base + 69632);
    float* stg = (float*)(base + 104448);
    float* sB1 = (float*)(base + 172032);
    float* sB2 = (float*)(base + 172544);

    const int tid = threadIdx.x;
    const int wid = tid >> 5;
    const int wm = wid & 3;
    const int wn = wid >> 2;
    const int row = tid >> 1;
    const int c0 = (tid & 1) * 64;
    const int n0 = blockIdx.x * 128;

    copy_tile<256>(T0, g_A1a, tid);
    copy_tile<256>(T1, g_A1b, tid);
    if (tid < 128) { sB1[tid] = ab1[tid]; sB2[tid] = ab2[tid]; }

    // A = h tile
    {
        const float4* srcp = (const float4*)(g_h + (size_t)(n0 + row) * 128 + c0);
        half* dh = sA + row * KP + c0;
#pragma unroll
        for (int g = 0; g < 16; ++g) {
            float4 v = srcp[g];
            *(uint2*)(dh + g * 4) = make_uint2(cvt2h(v.x, v.y), cvt2h(v.z, v.w));
        }
    }
    __syncthreads();

    FragC c[2][4];
#pragma unroll
    for (int i = 0; i < 2; ++i)
#pragma unroll
        for (int j = 0; j < 4; ++j) wmma::fill_fragment(c[i][j], 0.0f);
    gemm1p_256(sA, T0, c, wm, wn);     // h @ agg_w1[:128]
    __syncthreads();                   // A reads + T0 reads done

    // A = mean tile; T0 <- agg_w2
    {
        float inv = 1.0f / fmaxf(g_cnt[n0 + row], 1.0f);
        const float4* srcp = (const float4*)(g_msum + (size_t)(n0 + row) * 128 + c0);
        half* dh = sA + row * KP + c0;
#pragma unroll
        for (int g = 0; g < 16; ++g) {
            float4 v = srcp[g];
            *(uint2*)(dh + g * 4) = make_uint2(cvt2h(v.x * inv, v.y * inv),
                                               cvt2h(v.z * inv, v.w * inv));
        }
    }
    copy_tile<256>(T0, g_A2, tid);
    __syncthreads();

    gemm1p_256(sA, T1, c, wm, wn);     // += mean @ agg_w1[128:]
#pragma unroll
    for (int i = 0; i < 2; ++i)
#pragma unroll
        for (int j = 0; j < 4; ++j)
            wmma::store_matrix_sync(stg + (wm * 32 + i * 16) * SP + wn * 64 + j * 16,
                                    c[i][j], SP, wmma::mem_row_major);
    __syncthreads();

    // epilogue 1: m1 = silu(stg + ab1) -> sA
    {
        const float* st = stg + row * SP + c0;
        half* dh = sA + row * KP + c0;
#pragma unroll
        for (int g = 0; g < 16; ++g) {
            float4 v = *(const float4*)(st + g * 4);
            int cc = c0 + g * 4;
            float x0 = silu_f(v.x + sB1[cc + 0]);
            float x1 = silu_f(v.y + sB1[cc + 1]);
            float x2 = silu_f(v.z + sB1[cc + 2]);
            float x3 = silu_f(v.w + sB1[cc + 3]);
            *(uint2*)(dh + g * 4) = make_uint2(cvt2h(x0, x1), cvt2h(x2, x3));
        }
    }
    __syncthreads();

#pragma unroll
    for (int i = 0; i < 2; ++i)
#pragma unroll
        for (int j = 0; j < 4; ++j) wmma::fill_fragment(c[i][j], 0.0f);
    gemm1p_256(sA, T0, c, wm, wn);     // m1 @ agg_w2
#pragma unroll
    for (int i = 0; i < 2; ++i)
#pragma unroll
        for (int j = 0; j < 4; ++j)
            wmma::store_matrix_sync(stg + (wm * 32 + i * 16) * SP + wn * 64 + j * 16,
                                    c[i][j], SP, wmma::mem_row_major);
    __syncthreads();

    // epilogue 2: out = nf + silu(stg + ab2)
    {
        int n = n0 + row;
        if (n < N_NODES) {
            const float* st = stg + row * SP + c0;
            const float* nfp = nf + (size_t)n * 128 + c0;
            float* o = out + (size_t)n * 128 + c0;
#pragma unroll
            for (int g = 0; g < 16; ++g) {
                float4 v = *(const float4*)(st + g * 4);
                float4 f = *(const float4*)(nfp + g * 4);
                int cc = c0 + g * 4;
                float4 r;
                r.x = f.x + silu_f(v.x + sB2[cc + 0]);
                r.y = f.y + silu_f(v.y + sB2[cc + 1]);
                r.z = f.z + silu_f(v.z + sB2[cc + 2]);
                r.w = f.w + silu_f(v.w + sB2[cc + 3]);
                *(float4*)(o + g * 4) = r;
            }
        }
    }
}

// ---------------- launcher ----------------
extern "C" void kernel_launch(void* const* d_in, const int* in_sizes, int n_in,
                              void* d_out, int out_size) {
    (void)in_sizes; (void)n_in; (void)out_size;
    const float* nf  = (const float*)d_in[0];
    const float* ef  = (const float*)d_in[1];
    const float* gam = (const float*)d_in[2];
    const float* bet = (const float*)d_in[3];
    const float* mw1 = (const float*)d_in[4];
    const float* mb1 = (const float*)d_in[5];
    const float* mw2 = (const float*)d_in[6];
    const float* mb2 = (const float*)d_in[7];
    const float* aw1 = (const float*)d_in[8];
    const float* ab1 = (const float*)d_in[9];
    const float* aw2 = (const float*)d_in[10];
    const float* ab2 = (const float*)d_in[11];
    const int* eidx  = (const int*)d_in[12];
    const int* src = eidx;
    const int* dst = eidx + N_EDGES;
    float* out = (float*)d_out;

    cudaFuncSetAttribute(edge_persist_kernel, cudaFuncAttributeMaxDynamicSharedMemorySize, EDGE_SMEM);
    cudaFuncSetAttribute(agg_kernel,   cudaFuncAttributeMaxDynamicSharedMemorySize, AGG_SMEM);
    cudaFuncSetAttribute(pnode_kernel, cudaFuncAttributeMaxDynamicSharedMemorySize, PNODE_SMEM);

    const int NODE_TILES = NPAD / 128;  // 313

    zero_kernel<<<(NPAD * D / 4 + 255) / 256, 256>>>();
    ln_kernel<<<N_NODES / 8, 256>>>(nf, gam, bet);
    wprep_kernel<<<448, 256>>>(mw1, mw2, aw1, aw2);
    pnode_kernel<<<NODE_TILES, 256, PNODE_SMEM>>>();
    cnt_kernel<<<(N_EDGES + 255) / 256, 256>>>(src);
    edge_persist_kernel<<<152, 512, EDGE_SMEM>>>(ef, mb1, mb2, src, dst);
    agg_kernel<<<NODE_TILES, 256, AGG_SMEM>>>(nf, ab1, ab2, out);
}

// round 16
// speedup vs baseline: 2.2682x; 1.7303x over previous
#include <cuda_runtime.h>
#include <cuda_fp16.h>
#include <mma.h>
#include <cstdint>

using namespace nvcuda;

// Problem constants
#define N_NODES 40000
#define NPAD    40064
#define N_EDGES 640000
#define D 128

#define KP 136           // half elements per row in A/W tiles (pad 8) -> 272B rows
#define SP 132           // float elements per row in staging (pnode/agg)

// ---------------- device scratch ----------------
__device__ float g_h[NPAD * D];
__device__ float g_P[NPAD * 2 * D];
__device__ float g_msum[NPAD * D];
__device__ float g_cnt[NPAD];

// fp16 weight tiles, [n][KP] (B col-major), single fp16.
__device__ __align__(32) half g_W1c[128 * KP];    // msg_w1 rows [256,384)
__device__ __align__(32) half g_W2[128 * KP];     // msg_w2
__device__ __align__(32) half g_Wa[128 * KP];     // msg_w1 rows [0,128)
__device__ __align__(32) half g_Wb[128 * KP];     // msg_w1 rows [128,256)
__device__ __align__(32) half g_A1a[128 * KP];
__device__ __align__(32) half g_A1b[128 * KP];
__device__ __align__(32) half g_A2[128 * KP];

// ---------------- helpers ----------------
__device__ __forceinline__ float silu_f(float x) {
    float t;
    asm("tanh.approx.f32 %0, %1;" : "=f"(t) : "f"(x * 0.5f));
    return fmaf(0.5f * x, t, 0.5f * x);
}

__device__ __forceinline__ void red_add4(float* p, float a, float b, float c, float d) {
    asm volatile("red.global.add.v4.f32 [%0], {%1, %2, %3, %4};"
                 :: "l"(p), "f"(a), "f"(b), "f"(c), "f"(d) : "memory");
}

__device__ __forceinline__ void red_add2(float* p, float a, float b) {
    asm volatile("red.global.add.v2.f32 [%0], {%1, %2};"
                 :: "l"(p), "f"(a), "f"(b) : "memory");
}

__device__ __forceinline__ uint32_t cvt2h(float a, float b) {
    __half2 t = __float22half2_rn(make_float2(a, b));
    return *reinterpret_cast<uint32_t*>(&t);
}

__device__ __forceinline__ uint32_t smem_u32(const void* p) {
    uint32_t addr;
    asm("{ .reg .u64 tmp; cvta.to.shared.u64 tmp, %1; cvt.u32.u64 %0, tmp; }"
        : "=r"(addr) : "l"(p));
    return addr;
}

__device__ __forceinline__ uint32_t lds_u32(uint32_t addr) {
    uint32_t v;
    asm volatile("ld.shared.b32 %0, [%1];" : "=r"(v) : "r"(addr));
    return v;
}

__device__ __forceinline__ void sts_u32(uint32_t addr, uint32_t v) {
    asm volatile("st.shared.b32 [%0], %1;" :: "r"(addr), "r"(v) : "memory");
}

__device__ __forceinline__ void ldsm4(uint32_t r[4], uint32_t addr) {
    asm volatile("ldmatrix.sync.aligned.m8n8.x4.shared.b16 {%0,%1,%2,%3}, [%4];"
                 : "=r"(r[0]), "=r"(r[1]), "=r"(r[2]), "=r"(r[3]) : "r"(addr));
}

__device__ __forceinline__ void mma16816(float c[4], const uint32_t a[4], const uint32_t b[2]) {
    asm volatile("mma.sync.aligned.m16n8k16.row.col.f32.f16.f16.f32 "
                 "{%0,%1,%2,%3}, {%4,%5,%6,%7}, {%8,%9}, {%0,%1,%2,%3};"
                 : "+f"(c[0]), "+f"(c[1]), "+f"(c[2]), "+f"(c[3])
                 : "r"(a[0]), "r"(a[1]), "r"(a[2]), "r"(a[3]), "r"(b[0]), "r"(b[1]));
}

typedef wmma::fragment<wmma::accumulator, 16, 16, 16, float> FragC;
typedef wmma::fragment<wmma::matrix_a, 16, 16, 16, half, wmma::row_major> FragA;
typedef wmma::fragment<wmma::matrix_b, 16, 16, 16, half, wmma::col_major> FragB;

// single-product 32x64-per-warp (8 warps cover 128x128) — pnode/agg
__device__ __forceinline__ void gemm1p_256(const half* __restrict__ aH,
                                           const half* __restrict__ bW,
                                           FragC c[2][4], int wm, int wn) {
#pragma unroll
    for (int ks = 0; ks < 8; ++ks) {
        const int k0 = ks * 16;
        FragA ah[2];
#pragma unroll
        for (int i = 0; i < 2; ++i)
            wmma::load_matrix_sync(ah[i], aH + (wm * 32 + i * 16) * KP + k0, KP);
#pragma unroll
        for (int j = 0; j < 4; ++j) {
            FragB b;
            wmma::load_matrix_sync(b, bW + (wn * 64 + j * 16) * KP + k0, KP);
#pragma unroll
            for (int i = 0; i < 2; ++i)
                wmma::mma_sync(c[i][j], ah[i], b, c[i][j]);
        }
    }
}

// raw-mma GEMM: 32 rows x 32 cols per warp (16 warps cover 128x128),
// A via ldmatrix from smem (u32 base addr), B via u32 LDS from smem.
__device__ __forceinline__ void gemm_reg(uint32_t aBase, uint32_t bBase,
                                         float c[2][4][4],
                                         int wm, int wn, int lane) {
    const int g = lane >> 2, tig = lane & 3;
    const uint32_t arow = (uint32_t)(lane & 15);
    const uint32_t akk = (uint32_t)((lane >> 4) * 8);
#pragma unroll
    for (int ks = 0; ks < 8; ++ks) {
        const uint32_t k0 = ks * 16;
        uint32_t a[2][4];
#pragma unroll
        for (int i = 0; i < 2; ++i) {
            uint32_t addr = aBase +
                (((uint32_t)(wm * 32 + i * 16) + arow) * KP + k0 + akk) * 2;
            ldsm4(a[i], addr);
        }
#pragma unroll
        for (int j = 0; j < 4; ++j) {
            uint32_t bAddr = bBase +
                ((uint32_t)(wn * 32 + j * 8 + g) * KP + k0 + (uint32_t)(tig * 2)) * 2;
            uint32_t b[2];
            b[0] = lds_u32(bAddr);
            b[1] = lds_u32(bAddr + 16);   // k+8 halves = +16 bytes
            mma16816(c[0][j], a[0], b);
            mma16816(c[1][j], a[1], b);
        }
    }
}

template <int NTHR>
__device__ __forceinline__ void copy_tile(half* dst, const half* src, int tid) {
    uint4* d = (uint4*)dst;
    const uint4* s = (const uint4*)src;
    for (int idx = tid; idx < 2176; idx += NTHR) d[idx] = s[idx];
}

// ---------------- kernel: zero scratch ----------------
__global__ void zero_kernel() {
    int i = blockIdx.x * blockDim.x + threadIdx.x;
    const int total4 = NPAD * D / 4;
    if (i < total4) reinterpret_cast<float4*>(g_msum)[i] = make_float4(0.f, 0.f, 0.f, 0.f);
    if (i < NPAD) g_cnt[i] = 0.0f;
    if (i < (NPAD - N_NODES) * D / 4)
        reinterpret_cast<float4*>(g_h + N_NODES * D)[i] = make_float4(0.f, 0.f, 0.f, 0.f);
}

// ---------------- kernel: LayerNorm ----------------
__global__ void ln_kernel(const float* __restrict__ x,
                          const float* __restrict__ gamma,
                          const float* __restrict__ beta) {
    int warp = threadIdx.x >> 5;
    int lane = threadIdx.x & 31;
    int n = blockIdx.x * 8 + warp;
    float4 v = *reinterpret_cast<const float4*>(x + (size_t)n * D + lane * 4);
    float s = v.x + v.y + v.z + v.w;
#pragma unroll
    for (int o = 16; o > 0; o >>= 1) s += __shfl_xor_sync(0xffffffffu, s, o);
    float mu = s * (1.0f / D);
    float d0 = v.x - mu, d1 = v.y - mu, d2 = v.z - mu, d3 = v.w - mu;
    float ss = d0 * d0 + d1 * d1 + d2 * d2 + d3 * d3;
#pragma unroll
    for (int o = 16; o > 0; o >>= 1) ss += __shfl_xor_sync(0xffffffffu, ss, o);
    float rs = rsqrtf(ss * (1.0f / D) + 1e-5f);
    float4 g = *reinterpret_cast<const float4*>(gamma + lane * 4);
    float4 b = *reinterpret_cast<const float4*>(beta + lane * 4);
    float4 o4;
    o4.x = d0 * rs * g.x + b.x;
    o4.y = d1 * rs * g.y + b.y;
    o4.z = d2 * rs * g.z + b.z;
    o4.w = d3 * rs * g.w + b.w;
    *reinterpret_cast<float4*>(g_h + (size_t)n * D + lane * 4) = o4;
}

// ---------------- kernel: per-src edge counts ----------------
__global__ void cnt_kernel(const int* __restrict__ src) {
    int i = blockIdx.x * blockDim.x + threadIdx.x;
    if (i < N_EDGES) atomicAdd(&g_cnt[src[i]], 1.0f);
}

// ---------------- kernel: weight prep ----------------
__global__ void wprep_kernel(const float* __restrict__ mw1, const float* __restrict__ mw2,
                             const float* __restrict__ aw1, const float* __restrict__ aw2) {
    int i = blockIdx.x * blockDim.x + threadIdx.x;
    if (i >= 7 * 16384) return;
    int mat = i >> 14;
    int r = i & 16383;
    int n = r >> 7;
    int k = r & 127;
    int off = n * KP + k;
    switch (mat) {
        case 0: g_W1c[off] = __float2half_rn(mw1[(256 + k) * 128 + n]); break;
        case 1: g_W2[off]  = __float2half_rn(mw2[k * 128 + n]);         break;
        case 2: g_Wa[off]  = __float2half_rn(mw1[k * 128 + n]);         break;
        case 3: g_Wb[off]  = __float2half_rn(mw1[(128 + k) * 128 + n]); break;
        case 4: g_A1a[off] = __float2half_rn(aw1[k * 128 + n]);         break;
        case 5: g_A1b[off] = __float2half_rn(aw1[(128 + k) * 128 + n]); break;
        default: g_A2[off] = __float2half_rn(aw2[k * 128 + n]);         break;
    }
}

// ---------------- kernel: node projections P = h @ [Wa|Wb] ----------------
#define PNODE_SMEM (104448 + 1024)
__global__ __launch_bounds__(256, 2)
void pnode_kernel() {
    extern __shared__ char smraw[];
    char* base = (char*)(((uintptr_t)smraw + 255) & ~(uintptr_t)255);
    half* sWa = (half*)(base + 0);
    half* sWb = (half*)(base + 34816);
    half* sA  = (half*)(base + 69632);

    const int tid = threadIdx.x;
    const int wid = tid >> 5;
    const int wm = wid & 3;
    const int wn = wid >> 2;
    const int row = tid >> 1;
    const int c0 = (tid & 1) * 64;
    const int n0 = blockIdx.x * 128;

    copy_tile<256>(sWa, g_Wa, tid);
    copy_tile<256>(sWb, g_Wb, tid);

    {
        const float4* srcp = (const float4*)(g_h + (size_t)(n0 + row) * 128 + c0);
        half* dh = sA + row * KP + c0;
#pragma unroll
        for (int g = 0; g < 16; ++g) {
            float4 v = srcp[g];
            *(uint2*)(dh + g * 4) = make_uint2(cvt2h(v.x, v.y), cvt2h(v.z, v.w));
        }
    }
    __syncthreads();

#pragma unroll
    for (int hf = 0; hf < 2; ++hf) {
        FragC c[2][4];
#pragma unroll
        for (int i = 0; i < 2; ++i)
#pragma unroll
            for (int j = 0; j < 4; ++j) wmma::fill_fragment(c[i][j], 0.0f);
        gemm1p_256(sA, hf ? sWb : sWa, c, wm, wn);
#pragma unroll
        for (int i = 0; i < 2; ++i)
#pragma unroll
            for (int j = 0; j < 4; ++j)
                wmma::store_matrix_sync(
                    g_P + (size_t)(n0 + wm * 32 + i * 16) * 256 + hf * 128 + wn * 64 + j * 16,
                    c[i][j], 256, wmma::mem_row_major);
    }
}

// ---------------- persistent edge MLP + scatter (raw mma, reg epilogues) ----
// smem: W1 0 | W2 34816 | A 69632 | M1 104448 | sSrc 139264 | sDst 139776
#define SM_EW1  0
#define SM_EW2  34816
#define SM_EA   69632
#define SM_EM1  104448
#define SM_ESRC 139264
#define SM_EDST 139776
#define EDGE_SMEM (140288 + 1024)

__global__ __launch_bounds__(512, 1)
void edge_persist_kernel(const float* __restrict__ ef,
                         const float* __restrict__ b1, const float* __restrict__ b2,
                         const int* __restrict__ src, const int* __restrict__ dst) {
    extern __shared__ char smraw[];
    char* base = (char*)(((uintptr_t)smraw + 1023) & ~(uintptr_t)1023);

    half* sW1 = (half*)(base + SM_EW1);
    half* sW2 = (half*)(base + SM_EW2);
    half* sA  = (half*)(base + SM_EA);
    int*  sSrc = (int*)(base + SM_ESRC);
    int*  sDst = (int*)(base + SM_EDST);

    const uint32_t w1Base = smem_u32(base + SM_EW1);
    const uint32_t w2Base = smem_u32(base + SM_EW2);
    const uint32_t aBase  = smem_u32(base + SM_EA);
    const uint32_t m1Base = smem_u32(base + SM_EM1);
    const uint32_t srcBase = smem_u32(base + SM_ESRC);
    const uint32_t dstBase = smem_u32(base + SM_EDST);

    const int tid = threadIdx.x;
    const int wid = tid >> 5;
    const int lane = tid & 31;
    const int wm = wid & 3;
    const int wn = wid >> 2;
    const int row = tid >> 2;        // 0..127 (A-tile loader)
    const int c0 = (tid & 3) * 32;
    const int g = lane >> 2, tig = lane & 3;

    copy_tile<512>(sW1, g_W1c, tid);
    copy_tile<512>(sW2, g_W2, tid);

    // per-thread bias registers for the 4 column pairs this thread owns
    float2 bs1[4], bs2[4];
#pragma unroll
    for (int j = 0; j < 4; ++j) {
        int col = wn * 32 + j * 8 + tig * 2;
        bs1[j] = *(const float2*)(b1 + col);
        bs2[j] = *(const float2*)(b2 + col);
    }

    const int NT = N_EDGES / 128;  // 5000
    for (int t = blockIdx.x; t < NT; t += gridDim.x) {
        const int e0 = t * 128;
        __syncthreads();   // (a) prev tile's sM1/sA reads complete

        // A tile: ef rows -> fp16; indices; prefetches
        {
            const float4* srcp = (const float4*)(ef + (size_t)(e0 + row) * 128 + c0);
            half* dh = sA + row * KP + c0;
#pragma unroll
            for (int q = 0; q < 8; ++q) {
                float4 v = srcp[q];
                *(uint2*)(dh + q * 4) = make_uint2(cvt2h(v.x, v.y), cvt2h(v.z, v.w));
            }
        }
        if (tid < 128) {
            int s = src[e0 + tid], d = dst[e0 + tid];
            sSrc[tid] = s;
            sDst[tid] = d;
            const char* pa = (const char*)(g_P + (size_t)s * 256);
            const char* pb = (const char*)(g_P + (size_t)d * 256 + 128);
#pragma unroll
            for (int q = 0; q < 4; ++q) {
                asm volatile("prefetch.global.L2 [%0];" :: "l"(pa + q * 128));
                asm volatile("prefetch.global.L2 [%0];" :: "l"(pb + q * 128));
            }
        }
        {
            int nt2 = t + gridDim.x;
            if (nt2 < NT) {
                const char* nef = (const char*)ef + (size_t)nt2 * 128 * 512;
                asm volatile("prefetch.global.L2 [%0];" :: "l"(nef + tid * 128));
            }
        }
        __syncthreads();   // (b) sA / sSrc visible

        // ---- GEMM1 (registers): c = ef @ W1c ----
        float c[2][4][4];
#pragma unroll
        for (int i = 0; i < 2; ++i)
#pragma unroll
            for (int j = 0; j < 4; ++j)
#pragma unroll
                for (int q = 0; q < 4; ++q) c[i][j][q] = 0.0f;
        gemm_reg(aBase, w1Base, c, wm, wn, lane);

        // ---- epilogue 1 in registers: silu(c + Pa[src] + Pb[dst] + b1) -> sM1
#pragma unroll
        for (int i = 0; i < 2; ++i) {
            const int r0 = wm * 32 + i * 16 + g;
            const int r1 = r0 + 8;
            const int s0 = (int)lds_u32(srcBase + r0 * 4);
            const int d0 = (int)lds_u32(dstBase + r0 * 4);
            const int s1 = (int)lds_u32(srcBase + r1 * 4);
            const int d1 = (int)lds_u32(dstBase + r1 * 4);
            const float* pa0 = g_P + (size_t)s0 * 256;
            const float* pb0 = g_P + (size_t)d0 * 256 + 128;
            const float* pa1 = g_P + (size_t)s1 * 256;
            const float* pb1 = g_P + (size_t)d1 * 256 + 128;
#pragma unroll
            for (int j = 0; j < 4; ++j) {
                const int col = wn * 32 + j * 8 + tig * 2;
                float2 A0 = *(const float2*)(pa0 + col);
                float2 B0 = *(const float2*)(pb0 + col);
                float2 A1 = *(const float2*)(pa1 + col);
                float2 B1 = *(const float2*)(pb1 + col);
                float x0 = silu_f(c[i][j][0] + A0.x + B0.x + bs1[j].x);
                float x1 = silu_f(c[i][j][1] + A0.y + B0.y + bs1[j].y);
                float x2 = silu_f(c[i][j][2] + A1.x + B1.x + bs1[j].x);
                float x3 = silu_f(c[i][j][3] + A1.y + B1.y + bs1[j].y);
                sts_u32(m1Base + ((uint32_t)(r0 * KP + col)) * 2, cvt2h(x0, x1));
                sts_u32(m1Base + ((uint32_t)(r1 * KP + col)) * 2, cvt2h(x2, x3));
            }
        }
        __syncthreads();   // (c) sM1 visible

        // ---- GEMM2 (registers): c = m1 @ W2 ----
#pragma unroll
        for (int i = 0; i < 2; ++i)
#pragma unroll
            for (int j = 0; j < 4; ++j)
#pragma unroll
                for (int q = 0; q < 4; ++q) c[i][j][q] = 0.0f;
        gemm_reg(m1Base, w2Base, c, wm, wn, lane);

        // ---- epilogue 2 in registers: scatter silu(c + b2) into g_msum[src]
#pragma unroll
        for (int i = 0; i < 2; ++i) {
            const int r0 = wm * 32 + i * 16 + g;
            const int r1 = r0 + 8;
            const int s0 = (int)lds_u32(srcBase + r0 * 4);
            const int s1 = (int)lds_u32(srcBase + r1 * 4);
#pragma unroll
            for (int j = 0; j < 4; ++j) {
                const int col = wn * 32 + j * 8 + tig * 2;
                float y0 = silu_f(c[i][j][0] + bs2[j].x);
                float y1 = silu_f(c[i][j][1] + bs2[j].y);
                float y2 = silu_f(c[i][j][2] + bs2[j].x);
                float y3 = silu_f(c[i][j][3] + bs2[j].y);
                red_add2(g_msum + (size_t)s0 * 128 + col, y0, y1);
                red_add2(g_msum + (size_t)s1 * 128 + col, y2, y3);
            }
        }
    }
}

// ---------------- kernel: aggregation MLP + residual (single fp16 wmma) -----
#define AGG_SMEM (172032 + 1024 + 1024)
__global__ __launch_bounds__(256, 1)
void agg_kernel(const float* __restrict__ nf,
                const float* __restrict__ ab1, const float* __restrict__ ab2,
                float* __restrict__ out) {
    extern __shared__ char smraw[];
    char* base = (char*)(((uintptr_t)smraw + 1023) & ~(uintptr_t)1023);
    half* T0  = (half*)(base + 0);
    half* T1  = (half*)(base + 34816);
    half* sA  = (half*)(base + 69632);
    float* stg = (float*)(base + 104448);
    float* sB1 = (float*)(base + 172032);
    float* sB2 = (float*)(base + 172544);

    const int tid = threadIdx.x;
    const int wid = tid >> 5;
    const int wm = wid & 3;
    const int wn = wid >> 2;
    const int row = tid >> 1;
    const int c0 = (tid & 1) * 64;
    const int n0 = blockIdx.x * 128;

    copy_tile<256>(T0, g_A1a, tid);
    copy_tile<256>(T1, g_A1b, tid);
    if (tid < 128) { sB1[tid] = ab1[tid]; sB2[tid] = ab2[tid]; }

    {
        const float4* srcp = (const float4*)(g_h + (size_t)(n0 + row) * 128 + c0);
        half* dh = sA + row * KP + c0;
#pragma unroll
        for (int g = 0; g < 16; ++g) {
            float4 v = srcp[g];
            *(uint2*)(dh + g * 4) = make_uint2(cvt2h(v.x, v.y), cvt2h(v.z, v.w));
        }
    }
    __syncthreads();

    FragC c[2][4];
#pragma unroll
    for (int i = 0; i < 2; ++i)
#pragma unroll
        for (int j = 0; j < 4; ++j) wmma::fill_fragment(c[i][j], 0.0f);
    gemm1p_256(sA, T0, c, wm, wn);
    __syncthreads();

    {
        float inv = 1.0f / fmaxf(g_cnt[n0 + row], 1.0f);
        const float4* srcp = (const float4*)(g_msum + (size_t)(n0 + row) * 128 + c0);
        half* dh = sA + row * KP + c0;
#pragma unroll
        for (int g = 0; g < 16; ++g) {
            float4 v = srcp[g];
            *(uint2*)(dh + g * 4) = make_uint2(cvt2h(v.x * inv, v.y * inv),
                                               cvt2h(v.z * inv, v.w * inv));
        }
    }
    copy_tile<256>(T0, g_A2, tid);
    __syncthreads();

    gemm1p_256(sA, T1, c, wm, wn);
#pragma unroll
    for (int i = 0; i < 2; ++i)
#pragma unroll
        for (int j = 0; j < 4; ++j)
            wmma::store_matrix_sync(stg + (wm * 32 + i * 16) * SP + wn * 64 + j * 16,
                                    c[i][j], SP, wmma::mem_row_major);
    __syncthreads();

    {
        const float* st = stg + row * SP + c0;
        half* dh = sA + row * KP + c0;
#pragma unroll
        for (int g = 0; g < 16; ++g) {
            float4 v = *(const float4*)(st + g * 4);
            int cc = c0 + g * 4;
            float x0 = silu_f(v.x + sB1[cc + 0]);
            float x1 = silu_f(v.y + sB1[cc + 1]);
            float x2 = silu_f(v.z + sB1[cc + 2]);
            float x3 = silu_f(v.w + sB1[cc + 3]);
            *(uint2*)(dh + g * 4) = make_uint2(cvt2h(x0, x1), cvt2h(x2, x3));
        }
    }
    __syncthreads();

#pragma unroll
    for (int i = 0; i < 2; ++i)
#pragma unroll
        for (int j = 0; j < 4; ++j) wmma::fill_fragment(c[i][j], 0.0f);
    gemm1p_256(sA, T0, c, wm, wn);
#pragma unroll
    for (int i = 0; i < 2; ++i)
#pragma unroll
        for (int j = 0; j < 4; ++j)
            wmma::store_matrix_sync(stg + (wm * 32 + i * 16) * SP + wn * 64 + j * 16,
                                    c[i][j], SP, wmma::mem_row_major);
    __syncthreads();

    {
        int n = n0 + row;
        if (n < N_NODES) {
            const float* st = stg + row * SP + c0;
            const float* nfp = nf + (size_t)n * 128 + c0;
            float* o = out + (size_t)n * 128 + c0;
#pragma unroll
            for (int g = 0; g < 16; ++g) {
                float4 v = *(const float4*)(st + g * 4);
                float4 f = *(const float4*)(nfp + g * 4);
                int cc = c0 + g * 4;
                float4 r;
                r.x = f.x + silu_f(v.x + sB2[cc + 0]);
                r.y = f.y + silu_f(v.y + sB2[cc + 1]);
                r.z = f.z + silu_f(v.z + sB2[cc + 2]);
                r.w = f.w + silu_f(v.w + sB2[cc + 3]);
                *(float4*)(o + g * 4) = r;
            }
        }
    }
}

// ---------------- launcher ----------------
extern "C" void kernel_launch(void* const* d_in, const int* in_sizes, int n_in,
                              void* d_out, int out_size) {
    (void)in_sizes; (void)n_in; (void)out_size;
    const float* nf  = (const float*)d_in[0];
    const float* ef  = (const float*)d_in[1];
    const float* gam = (const float*)d_in[2];
    const float* bet = (const float*)d_in[3];
    const float* mw1 = (const float*)d_in[4];
    const float* mb1 = (const float*)d_in[5];
    const float* mw2 = (const float*)d_in[6];
    const float* mb2 = (const float*)d_in[7];
    const float* aw1 = (const float*)d_in[8];
    const float* ab1 = (const float*)d_in[9];
    const float* aw2 = (const float*)d_in[10];
    const float* ab2 = (const float*)d_in[11];
    const int* eidx  = (const int*)d_in[12];
    const int* src = eidx;
    const int* dst = eidx + N_EDGES;
    float* out = (float*)d_out;

    cudaFuncSetAttribute(edge_persist_kernel, cudaFuncAttributeMaxDynamicSharedMemorySize, EDGE_SMEM);
    cudaFuncSetAttribute(agg_kernel,   cudaFuncAttributeMaxDynamicSharedMemorySize, AGG_SMEM);
    cudaFuncSetAttribute(pnode_kernel, cudaFuncAttributeMaxDynamicSharedMemorySize, PNODE_SMEM);

    const int NODE_TILES = NPAD / 128;  // 313

    zero_kernel<<<(NPAD * D / 4 + 255) / 256, 256>>>();
    ln_kernel<<<N_NODES / 8, 256>>>(nf, gam, bet);
    wprep_kernel<<<448, 256>>>(mw1, mw2, aw1, aw2);
    pnode_kernel<<<NODE_TILES, 256, PNODE_SMEM>>>();
    cnt_kernel<<<(N_EDGES + 255) / 256, 256>>>(src);
    edge_persist_kernel<<<152, 512, EDGE_SMEM>>>(ef, mb1, mb2, src, dst);
    agg_kernel<<<NODE_TILES, 256, AGG_SMEM>>>(nf, ab1, ab2, out);
}